// round 15
// baseline (speedup 1.0000x reference)
#include <cuda_runtime.h>
#include <cuda_bf16.h>
#include <math.h>
#include <stdint.h>

#define NS   2048
#define NH   16
#define DH   64
#define DIMM 1024
#define LDQ  6144

__device__ __constant__ float SCALE = 0.125f;

// ---- scratch ----
__device__ __nv_bfloat16 g_qh [(size_t)NS * LDQ];
__device__ __nv_bfloat16 g_ql [(size_t)NS * LDQ];
__device__ __nv_bfloat16 g_xh [(size_t)NS * DIMM];
__device__ __nv_bfloat16 g_xl [(size_t)NS * DIMM];
__device__ __nv_bfloat16 g_wqh[(size_t)LDQ * DIMM];
__device__ __nv_bfloat16 g_wql[(size_t)LDQ * DIMM];
__device__ __nv_bfloat16 g_t1h[(size_t)NH * NS * NS];
__device__ __nv_bfloat16 g_t1l[(size_t)NH * NS * NS];
__device__ __nv_bfloat16 g_lkh[(size_t)NH * NS * NS];
__device__ __nv_bfloat16 g_lkl[(size_t)NH * NS * NS];
__device__ float g_sc [(size_t)NH * NS * NS];
__device__ __nv_bfloat16 g_vth[(size_t)NH * DH * NS];
__device__ __nv_bfloat16 g_vtl[(size_t)NH * DH * NS];
__device__ __nv_bfloat16 g_cth[(size_t)NS * DIMM];
__device__ __nv_bfloat16 g_ctl[(size_t)NS * DIMM];
__device__ __nv_bfloat16 g_woh[(size_t)DIMM * DIMM];
__device__ __nv_bfloat16 g_wol[(size_t)DIMM * DIMM];

// ============================================================
// helpers
// ============================================================
__device__ __forceinline__ uint32_t smem_u32(const void* p) {
    uint32_t a;
    asm("{ .reg .u64 t; cvta.to.shared.u64 t, %1; cvt.u32.u64 %0, t; }" : "=r"(a) : "l"(p));
    return a;
}

#define CPASYNC16(s, g) \
    asm volatile("cp.async.cg.shared.global [%0], [%1], 16;" :: "r"(s), "l"(g) : "memory")
#define CP_COMMIT() asm volatile("cp.async.commit_group;" ::: "memory")
#define CP_WAIT0()  asm volatile("cp.async.wait_group 0;" ::: "memory")
#define CP_WAIT1()  asm volatile("cp.async.wait_group 1;" ::: "memory")

#define LDMX4(r, addr) \
    asm volatile("ldmatrix.sync.aligned.m8n8.x4.shared.b16 {%0,%1,%2,%3}, [%4];" \
        : "=r"((r)[0]), "=r"((r)[1]), "=r"((r)[2]), "=r"((r)[3]) : "r"(addr))

#define MMA16816(d, a, b0, b1) \
    asm("mma.sync.aligned.m16n8k16.row.col.f32.bf16.bf16.f32 " \
        "{%0,%1,%2,%3}, {%4,%5,%6,%7}, {%8,%9}, {%0,%1,%2,%3};" \
        : "+f"((d)[0]), "+f"((d)[1]), "+f"((d)[2]), "+f"((d)[3]) \
        : "r"((a)[0]), "r"((a)[1]), "r"((a)[2]), "r"((a)[3]), "r"(b0), "r"(b1))

__device__ __forceinline__ uint32_t pack_bf2(float a, float b) {
    __nv_bfloat162 t = __floats2bfloat162_rn(a, b);
    return *(uint32_t*)&t;
}
__device__ __forceinline__ void split1(float v, __nv_bfloat16& h, float& r) {
    h = __float2bfloat16_rn(v);
    r = v - __bfloat162float(h);
}
__device__ __forceinline__ float fast_sigmoid(float x) {
    return __fdividef(1.0f, 1.0f + __expf(-x));
}
__device__ __forceinline__ float fast_silu(float x) {
    return __fdividef(x, 1.0f + __expf(-x));
}

// 32-wide K chunks: 64B data + 16B pad per row
#define PADB   80
#define TILEB  (128 * PADB)      // 10240
#define BUFB   (4 * TILEB)       // 40960
#define DBUF_SMEM (2 * BUFB)     // 81920 -> 2 CTAs/SM
#define AV_STAGE  (384 * PADB)   // 30720
#define AV_SMEM2  (2 * AV_STAGE) // 61440 -> 3 CTAs/SM

// qkv: 64x128 CTA tile, 3 CTAs/SM
#define QK_AH   0
#define QK_AL   (64 * PADB)
#define QK_BH   (2 * 64 * PADB)
#define QK_BL   (QK_BH + 128 * PADB)
#define QK_STAGE (QK_BH + 2 * 128 * PADB)  // 30720
#define QK_SMEM  (2 * QK_STAGE)            // 61440 -> 3 CTAs/SM

// head13 merged kernel: one-shot K=64 tiles, 144B rows (128B data + 16B pad)
#define H13_PAD  144
#define H13_T    (128 * H13_PAD)   // 18432
#define H13_SMEM (6 * H13_T)       // 110592 -> 2 CTAs/SM

// ============================================================
// chunk compute: 128x128 tile, warp 64x32, K=32 per chunk (3 passes)
// ============================================================
__device__ __forceinline__ void mma_chunk_128(
    uint32_t aH, uint32_t aL, uint32_t bH, uint32_t bL,
    int m0, int n0, int lrow, uint32_t lkoff, float acc[4][4][4])
{
#pragma unroll
    for (int kk = 0; kk < 2; kk++) {
        const uint32_t ko = kk * 32 + lkoff;
        uint32_t ah[4][4], al[4][4];
        const uint32_t aoff = (uint32_t)((m0 + lrow) * PADB) + ko;
#pragma unroll
        for (int tm = 0; tm < 4; tm++) {
            LDMX4(ah[tm], aH + aoff + tm * 16 * PADB);
            LDMX4(al[tm], aL + aoff + tm * 16 * PADB);
        }
        uint32_t bh[2][4], bl[2][4];
        const uint32_t boff = (uint32_t)((n0 + lrow) * PADB) + ko;
#pragma unroll
        for (int tp = 0; tp < 2; tp++) {
            LDMX4(bh[tp], bH + boff + tp * 16 * PADB);
            LDMX4(bl[tp], bL + boff + tp * 16 * PADB);
        }
#pragma unroll
        for (int tm = 0; tm < 4; tm++)
#pragma unroll
            for (int tn = 0; tn < 4; tn++) {
                const int tp = tn >> 1, sel = tn & 1;
                MMA16816(acc[tm][tn], ah[tm], bh[tp][sel], bh[tp][sel + 2]);
            }
#pragma unroll
        for (int tm = 0; tm < 4; tm++)
#pragma unroll
            for (int tn = 0; tn < 4; tn++) {
                const int tp = tn >> 1, sel = tn & 1;
                MMA16816(acc[tm][tn], ah[tm], bl[tp][sel], bl[tp][sel + 2]);
            }
#pragma unroll
        for (int tm = 0; tm < 4; tm++)
#pragma unroll
            for (int tn = 0; tn < 4; tn++) {
                const int tp = tn >> 1, sel = tn & 1;
                MMA16816(acc[tm][tn], al[tm], bh[tp][sel], bh[tp][sel + 2]);
            }
    }
}

// one-shot K=64 version on 144B rows
__device__ __forceinline__ void mma_k64_144(
    uint32_t aH, uint32_t aL, uint32_t bH, uint32_t bL,
    int m0, int n0, int lrow, uint32_t lkoff, float acc[4][4][4])
{
#pragma unroll
    for (int kk = 0; kk < 4; kk++) {
        const uint32_t ko = kk * 32 + lkoff;
        uint32_t ah[4][4], al[4][4];
        const uint32_t aoff = (uint32_t)((m0 + lrow) * H13_PAD) + ko;
#pragma unroll
        for (int tm = 0; tm < 4; tm++) {
            LDMX4(ah[tm], aH + aoff + tm * 16 * H13_PAD);
            LDMX4(al[tm], aL + aoff + tm * 16 * H13_PAD);
        }
        uint32_t bh[2][4], bl[2][4];
        const uint32_t boff = (uint32_t)((n0 + lrow) * H13_PAD) + ko;
#pragma unroll
        for (int tp = 0; tp < 2; tp++) {
            LDMX4(bh[tp], bH + boff + tp * 16 * H13_PAD);
            LDMX4(bl[tp], bL + boff + tp * 16 * H13_PAD);
        }
#pragma unroll
        for (int tm = 0; tm < 4; tm++)
#pragma unroll
            for (int tn = 0; tn < 4; tn++) {
                const int tp = tn >> 1, sel = tn & 1;
                MMA16816(acc[tm][tn], ah[tm], bh[tp][sel], bh[tp][sel + 2]);
            }
#pragma unroll
        for (int tm = 0; tm < 4; tm++)
#pragma unroll
            for (int tn = 0; tn < 4; tn++) {
                const int tp = tn >> 1, sel = tn & 1;
                MMA16816(acc[tm][tn], ah[tm], bl[tp][sel], bl[tp][sel + 2]);
            }
#pragma unroll
        for (int tm = 0; tm < 4; tm++)
#pragma unroll
            for (int tn = 0; tn < 4; tn++) {
                const int tp = tn >> 1, sel = tn & 1;
                MMA16816(acc[tm][tn], al[tm], bh[tp][sel], bh[tp][sel + 2]);
            }
    }
}

#define ISSUE_128(c, gsrc, ld, sdst)                                      \
    do {                                                                  \
        const __nv_bfloat16* gp_ = (gsrc) + (size_t)(c) * 32;             \
        const uint32_t sb_ = (sdst) + ((c) & 1) * BUFB;                   \
        _Pragma("unroll")                                                 \
        for (int kq = 0; kq < 8; kq++)                                    \
            CPASYNC16(sb_ + kq * 16 * PADB, gp_ + (size_t)(kq * 16) * (ld)); \
        CP_COMMIT();                                                      \
    } while (0)

// warp tile 32x32 chunk compute
__device__ __forceinline__ void mma_chunk_64(
    uint32_t aH, uint32_t aL, uint32_t bH, uint32_t bL,
    int m0, int n0, int lrow, uint32_t lkoff, float acc[2][4][4])
{
#pragma unroll
    for (int kk = 0; kk < 2; kk++) {
        const uint32_t ko = kk * 32 + lkoff;
        uint32_t ah[2][4], al[2][4];
        const uint32_t aoff = (uint32_t)((m0 + lrow) * PADB) + ko;
#pragma unroll
        for (int tm = 0; tm < 2; tm++) {
            LDMX4(ah[tm], aH + aoff + tm * 16 * PADB);
            LDMX4(al[tm], aL + aoff + tm * 16 * PADB);
        }
        uint32_t bh[2][4], bl[2][4];
        const uint32_t boff = (uint32_t)((n0 + lrow) * PADB) + ko;
#pragma unroll
        for (int tp = 0; tp < 2; tp++) {
            LDMX4(bh[tp], bH + boff + tp * 16 * PADB);
            LDMX4(bl[tp], bL + boff + tp * 16 * PADB);
        }
#pragma unroll
        for (int tm = 0; tm < 2; tm++)
#pragma unroll
            for (int tn = 0; tn < 4; tn++) {
                const int tp = tn >> 1, sel = tn & 1;
                MMA16816(acc[tm][tn], ah[tm], bh[tp][sel], bh[tp][sel + 2]);
            }
#pragma unroll
        for (int tm = 0; tm < 2; tm++)
#pragma unroll
            for (int tn = 0; tn < 4; tn++) {
                const int tp = tn >> 1, sel = tn & 1;
                MMA16816(acc[tm][tn], ah[tm], bl[tp][sel], bl[tp][sel + 2]);
            }
#pragma unroll
        for (int tm = 0; tm < 2; tm++)
#pragma unroll
            for (int tn = 0; tn < 4; tn++) {
                const int tp = tn >> 1, sel = tn & 1;
                MMA16816(acc[tm][tn], al[tm], bh[tp][sel], bh[tp][sel + 2]);
            }
    }
}

// ============================================================
// conversion kernels
// ============================================================
__global__ void conv_split(const float* __restrict__ src,
                           __nv_bfloat16* __restrict__ hi, __nv_bfloat16* __restrict__ lo,
                           int n) {
    int i = blockIdx.x * 256 + threadIdx.x;
    if (i >= n) return;
    float v = src[i];
    __nv_bfloat16 h; float r;
    split1(v, h, r);
    hi[i] = h;
    lo[i] = __float2bfloat16_rn(r);
}

__global__ void conv_split_T(const float* __restrict__ src,
                             __nv_bfloat16* __restrict__ hi, __nv_bfloat16* __restrict__ lo,
                             int R, int C) {
    __shared__ float tile[32][33];
    const int bx = blockIdx.x * 32, by = blockIdx.y * 32;
    const int tx = threadIdx.x, ty = threadIdx.y;
#pragma unroll
    for (int i = 0; i < 32; i += 8)
        tile[ty + i][tx] = src[(size_t)(by + ty + i) * C + bx + tx];
    __syncthreads();
#pragma unroll
    for (int i = 0; i < 32; i += 8) {
        float v = tile[tx][ty + i];
        __nv_bfloat16 h; float r;
        split1(v, h, r);
        size_t o = (size_t)(bx + ty + i) * R + by + tx;
        hi[o] = h;
        lo[o] = __float2bfloat16_rn(r);
    }
}

__global__ void conv_vT(const __nv_bfloat16* __restrict__ QH,
                        const __nv_bfloat16* __restrict__ QL,
                        __nv_bfloat16* __restrict__ hi, __nv_bfloat16* __restrict__ lo) {
    __shared__ float tile[32][33];
    const int h = blockIdx.z;
    const int bx = blockIdx.x * 32;
    const int by = blockIdx.y * 32;
    const int tx = threadIdx.x, ty = threadIdx.y;
#pragma unroll
    for (int i = 0; i < 32; i += 8) {
        size_t o = (size_t)(bx + ty + i) * LDQ + 5 * 1024 + h * DH + by + tx;
        tile[ty + i][tx] = __bfloat162float(QH[o]) + __bfloat162float(QL[o]);
    }
    __syncthreads();
#pragma unroll
    for (int i = 0; i < 32; i += 8) {
        float v = tile[tx][ty + i];
        __nv_bfloat16 hh; float r;
        split1(v, hh, r);
        size_t o = (size_t)(h * DH + by + ty + i) * NS + bx + tx;
        hi[o] = hh;
        lo[o] = __float2bfloat16_rn(r);
    }
}

// ============================================================
// qkv = x @ Wqkv — 64x128 tiles, 3 CTAs/SM
// ============================================================
__global__ void __launch_bounds__(256, 3) qkv_mma(
    const __nv_bfloat16* __restrict__ XH, const __nv_bfloat16* __restrict__ XL,
    const __nv_bfloat16* __restrict__ WH, const __nv_bfloat16* __restrict__ WL,
    __nv_bfloat16* __restrict__ QH, __nv_bfloat16* __restrict__ QL)
{
    const int bm = blockIdx.y;
    const int bn = blockIdx.x;
    extern __shared__ char sm[];
    const uint32_t smb = smem_u32(sm);
    const int t = threadIdx.x;
    const int wid = t >> 5, lane = t & 31;
    const int m0 = (wid & 1) * 32;
    const int n0 = (wid >> 1) * 32;

    const int isB   = t >> 7;
    const int g     = t & 127;
    const int a_row = g >> 1;
    const int a_c0  = (g & 1) * 2;
    const int b_row = g >> 2;
    const int b_c0  = g & 3;

    const __nv_bfloat16* pAh = XH + (size_t)(bm * 64 + a_row) * DIMM + a_c0 * 8;
    const __nv_bfloat16* pAl = XL + (size_t)(bm * 64 + a_row) * DIMM + a_c0 * 8;
    const __nv_bfloat16* pBh = WH + (size_t)(bn * 128 + b_row) * DIMM + b_c0 * 8;
    const __nv_bfloat16* pBl = WL + (size_t)(bn * 128 + b_row) * DIMM + b_c0 * 8;
    const uint32_t sAh = smb + QK_AH + a_row * PADB + a_c0 * 16;
    const uint32_t sAl = smb + QK_AL + a_row * PADB + a_c0 * 16;
    const uint32_t sBh = smb + QK_BH + b_row * PADB + b_c0 * 16;
    const uint32_t sBl = smb + QK_BL + b_row * PADB + b_c0 * 16;

#define QK_ISSUE(c)                                                           \
    do {                                                                      \
        const size_t kofs = (size_t)(c) * 32;                                 \
        const uint32_t bb = ((c) & 1) * QK_STAGE;                             \
        if (!isB) {                                                           \
            CPASYNC16(sAh + bb,      pAh + kofs);                             \
            CPASYNC16(sAh + bb + 16, pAh + kofs + 8);                         \
            CPASYNC16(sAl + bb,      pAl + kofs);                             \
            CPASYNC16(sAl + bb + 16, pAl + kofs + 8);                         \
        } else {                                                              \
            _Pragma("unroll")                                                 \
            for (int q = 0; q < 4; q++) {                                     \
                CPASYNC16(sBh + bb + q * 32 * PADB,                           \
                          pBh + kofs + (size_t)(q * 32) * DIMM);              \
                CPASYNC16(sBl + bb + q * 32 * PADB,                           \
                          pBl + kofs + (size_t)(q * 32) * DIMM);              \
            }                                                                 \
        }                                                                     \
        CP_COMMIT();                                                          \
    } while (0)

    QK_ISSUE(0);

    float acc[2][4][4] = {};
    const int lrow = lane & 15;
    const uint32_t lkoff = (uint32_t)((lane >> 4) * 16);

    for (int c = 0; c < 32; c++) {
        CP_WAIT0();
        __syncthreads();
        if (c + 1 < 32) QK_ISSUE(c + 1);
        const uint32_t bb = smb + (c & 1) * QK_STAGE;
        mma_chunk_64(bb + QK_AH, bb + QK_AL, bb + QK_BH, bb + QK_BL,
                     m0, n0, lrow, lkoff, acc);
    }

    const int gq = lane >> 2;
    const int tg = lane & 3;
#pragma unroll
    for (int tm = 0; tm < 2; tm++) {
#pragma unroll
        for (int tn = 0; tn < 4; tn++) {
            const int i0 = bm * 64 + m0 + tm * 16 + gq;
            const int j0 = bn * 128 + n0 + tn * 8 + tg * 2;
            float v0 = acc[tm][tn][0], v1 = acc[tm][tn][1];
            float v2 = acc[tm][tn][2], v3 = acc[tm][tn][3];
            size_t o0 = (size_t)i0 * LDQ + j0;
            size_t o1 = o0 + (size_t)8 * LDQ;
            __nv_bfloat16 h; float r0, r1, r2, r3;
            split1(v0, h, r0); split1(v1, h, r1); split1(v2, h, r2); split1(v3, h, r3);
            *(uint32_t*)(QH + o0) = pack_bf2(v0, v1);
            *(uint32_t*)(QH + o1) = pack_bf2(v2, v3);
            *(uint32_t*)(QL + o0) = pack_bf2(r0, r1);
            *(uint32_t*)(QL + o1) = pack_bf2(r2, r3);
        }
    }
}

// ============================================================
// Merged head1+head3: A = qc (shared), B1 = vu -> term1 (bf16 split),
// B2 = kc -> Sc (fp32). One-shot K=64 smem, sequential epilogues
// reusing the same accumulator registers.
// ============================================================
__global__ void __launch_bounds__(256, 2) head13_mma(
    const __nv_bfloat16* __restrict__ QH, const __nv_bfloat16* __restrict__ QL,
    __nv_bfloat16* __restrict__ T1H, __nv_bfloat16* __restrict__ T1L,
    float* __restrict__ CF)
{
    const int h  = blockIdx.z;
    const int bi = blockIdx.y, bj = blockIdx.x;
    if (bj > bi) return;

    extern __shared__ char sm[];
    const uint32_t smb = smem_u32(sm);
    const int t = threadIdx.x;
    const int wid = t >> 5, lane = t & 31;
    const int m0 = (wid & 1) * 64;
    const int n0 = (wid >> 1) * 32;

    // one-shot loader: 6 tiles (Ah,Al,B1h,B1l,B2h,B2l), 128 rows x 8 cols(16B)
    {
        const int col  = t & 7;
        const int row0 = t >> 3;          // 0..31
        const size_t colo = (size_t)col * 8;
        const __nv_bfloat16* gA  = QH + (size_t)(bi * 128) * LDQ + 3 * 1024 + h * DH + colo;
        const __nv_bfloat16* gAl = QL + (size_t)(bi * 128) * LDQ + 3 * 1024 + h * DH + colo;
        const __nv_bfloat16* gB1 = QH + (size_t)(bj * 128) * LDQ + 2 * 1024 + h * DH + colo;
        const __nv_bfloat16* gB1l= QL + (size_t)(bj * 128) * LDQ + 2 * 1024 + h * DH + colo;
        const __nv_bfloat16* gB2 = QH + (size_t)(bj * 128) * LDQ + 4 * 1024 + h * DH + colo;
        const __nv_bfloat16* gB2l= QL + (size_t)(bj * 128) * LDQ + 4 * 1024 + h * DH + colo;
        const uint32_t so = row0 * H13_PAD + col * 16;
#pragma unroll
        for (int q = 0; q < 4; q++) {
            const size_t ro = (size_t)(row0 + q * 32) * LDQ;
            const uint32_t sro = q * 32 * H13_PAD;
            CPASYNC16(smb + 0 * H13_T + so + sro, gA   + ro);
            CPASYNC16(smb + 1 * H13_T + so + sro, gAl  + ro);
            CPASYNC16(smb + 2 * H13_T + so + sro, gB1  + ro);
            CPASYNC16(smb + 3 * H13_T + so + sro, gB1l + ro);
            CPASYNC16(smb + 4 * H13_T + so + sro, gB2  + ro);
            CPASYNC16(smb + 5 * H13_T + so + sro, gB2l + ro);
        }
        CP_COMMIT();
    }
    CP_WAIT0();
    __syncthreads();

    const size_t hb = (size_t)h * NS * NS;
    const int lrow = lane & 15;
    const uint32_t lkoff = (uint32_t)((lane >> 4) * 16);
    const int g  = lane >> 2;
    const int tg = lane & 3;

    float acc[4][4][4];

    // ---- phase 1: term1 = tril(qc_s @ vu^T) ----
#pragma unroll
    for (int a = 0; a < 4; a++)
#pragma unroll
        for (int b = 0; b < 4; b++)
#pragma unroll
            for (int q = 0; q < 4; q++) acc[a][b][q] = 0.0f;

    mma_k64_144(smb + 0 * H13_T, smb + 1 * H13_T, smb + 2 * H13_T, smb + 3 * H13_T,
                m0, n0, lrow, lkoff, acc);

#pragma unroll
    for (int tm = 0; tm < 4; tm++) {
#pragma unroll
        for (int tn = 0; tn < 4; tn++) {
            const int i0 = bi * 128 + m0 + tm * 16 + g;
            const int j0 = bj * 128 + n0 + tn * 8 + tg * 2;
            float v[4];
            v[0] = acc[tm][tn][0] * SCALE; v[1] = acc[tm][tn][1] * SCALE;
            v[2] = acc[tm][tn][2] * SCALE; v[3] = acc[tm][tn][3] * SCALE;
            const int ii[4] = {i0, i0, i0 + 8, i0 + 8};
            const int jj[4] = {j0, j0 + 1, j0, j0 + 1};
#pragma unroll
            for (int q = 0; q < 4; q++)
                v[q] = (jj[q] <= ii[q]) ? v[q] : 0.0f;
            size_t o0 = hb + (size_t)i0 * NS + j0;
            size_t o1 = o0 + (size_t)8 * NS;
            __nv_bfloat16 hh; float r[4];
            split1(v[0], hh, r[0]); split1(v[1], hh, r[1]);
            split1(v[2], hh, r[2]); split1(v[3], hh, r[3]);
            *(uint32_t*)(T1H + o0) = pack_bf2(v[0], v[1]);
            *(uint32_t*)(T1H + o1) = pack_bf2(v[2], v[3]);
            *(uint32_t*)(T1L + o0) = pack_bf2(r[0], r[1]);
            *(uint32_t*)(T1L + o1) = pack_bf2(r[2], r[3]);
        }
    }

    // ---- phase 2: Sc = qc_s @ kc^T (reuse acc regs) ----
#pragma unroll
    for (int a = 0; a < 4; a++)
#pragma unroll
        for (int b = 0; b < 4; b++)
#pragma unroll
            for (int q = 0; q < 4; q++) acc[a][b][q] = 0.0f;

    mma_k64_144(smb + 0 * H13_T, smb + 1 * H13_T, smb + 4 * H13_T, smb + 5 * H13_T,
                m0, n0, lrow, lkoff, acc);

#pragma unroll
    for (int tm = 0; tm < 4; tm++) {
#pragma unroll
        for (int tn = 0; tn < 4; tn++) {
            const int i0 = bi * 128 + m0 + tm * 16 + g;
            const int j0 = bj * 128 + n0 + tn * 8 + tg * 2;
            size_t o0 = hb + (size_t)i0 * NS + j0;
            size_t o1 = o0 + (size_t)8 * NS;
            *(float2*)(CF + o0) = make_float2(acc[tm][tn][0] * SCALE, acc[tm][tn][1] * SCALE);
            *(float2*)(CF + o1) = make_float2(acc[tm][tn][2] * SCALE, acc[tm][tn][3] * SCALE);
        }
    }
}

// ============================================================
// head2 (lookahead): 128x128, 2 CTAs/SM (unchanged structure)
// ============================================================
__global__ void __launch_bounds__(256, 2) head2_mma(
    const __nv_bfloat16* __restrict__ QH, const __nv_bfloat16* __restrict__ QL,
    __nv_bfloat16* __restrict__ CH, __nv_bfloat16* __restrict__ CL)
{
    const int h  = blockIdx.z;
    const int bi = blockIdx.y, bj = blockIdx.x;
    if (bj < bi) return;

    extern __shared__ char sm[];
    const uint32_t smb = smem_u32(sm);
    const int t = threadIdx.x;
    const int wid = t >> 5, lane = t & 31;
    const int m0 = (wid & 1) * 64;
    const int n0 = (wid >> 1) * 32;

    const int grp  = t >> 6;
    const int gg   = t & 63;
    const int col  = gg & 3;
    const int row0 = gg >> 2;
    const __nv_bfloat16* base;
    if (grp == 0)      base = QH + (size_t)(bi * 128) * LDQ + 0 * 1024 + h * DH;
    else if (grp == 1) base = QL + (size_t)(bi * 128) * LDQ + 0 * 1024 + h * DH;
    else if (grp == 2) base = QH + (size_t)(bj * 128) * LDQ + 1 * 1024 + h * DH;
    else               base = QL + (size_t)(bj * 128) * LDQ + 1 * 1024 + h * DH;
    const __nv_bfloat16* gsrc = base + (size_t)row0 * LDQ + col * 8;
    const uint32_t sdst = smb + grp * TILEB + row0 * PADB + col * 16;

    ISSUE_128(0, gsrc, LDQ, sdst);
    ISSUE_128(1, gsrc, LDQ, sdst);

    float acc[4][4][4] = {};
    const int lrow = lane & 15;
    const uint32_t lkoff = (uint32_t)((lane >> 4) * 16);

    CP_WAIT1();
    __syncthreads();
    {
        const uint32_t bse = smb;
        mma_chunk_128(bse, bse + TILEB, bse + 2 * TILEB, bse + 3 * TILEB,
                      m0, n0, lrow, lkoff, acc);
    }
    CP_WAIT0();
    __syncthreads();
    {
        const uint32_t bse = smb + BUFB;
        mma_chunk_128(bse, bse + TILEB, bse + 2 * TILEB, bse + 3 * TILEB,
                      m0, n0, lrow, lkoff, acc);
    }

    const size_t hb = (size_t)h * NS * NS;
    const int g  = lane >> 2;
    const int tg = lane & 3;
#pragma unroll
    for (int tm = 0; tm < 4; tm++) {
#pragma unroll
        for (int tn = 0; tn < 4; tn++) {
            const int i0 = bi * 128 + m0 + tm * 16 + g;
            const int j0 = bj * 128 + n0 + tn * 8 + tg * 2;
            float v[4];
            v[0] = acc[tm][tn][0] * SCALE; v[1] = acc[tm][tn][1] * SCALE;
            v[2] = acc[tm][tn][2] * SCALE; v[3] = acc[tm][tn][3] * SCALE;
            const int ii[4] = {i0, i0, i0 + 8, i0 + 8};
            const int jj[4] = {j0, j0 + 1, j0, j0 + 1};
#pragma unroll
            for (int q = 0; q < 4; q++)
                v[q] = (jj[q] > ii[q]) ? fast_sigmoid(v[q]) : 0.0f;
            size_t o0 = hb + (size_t)i0 * NS + j0;
            size_t o1 = o0 + (size_t)8 * NS;
            __nv_bfloat16 hh; float r[4];
            split1(v[0], hh, r[0]); split1(v[1], hh, r[1]);
            split1(v[2], hh, r[2]); split1(v[3], hh, r[3]);
            *(uint32_t*)(CH + o0) = pack_bf2(v[0], v[1]);
            *(uint32_t*)(CH + o1) = pack_bf2(v[2], v[3]);
            *(uint32_t*)(CL + o0) = pack_bf2(r[0], r[1]);
            *(uint32_t*)(CL + o1) = pack_bf2(r[2], r[3]);
        }
    }
}

// ============================================================
// Su (128x128, 2 CTAs/SM), fused SC -= silu(Su).
// Work-descending CTA order: longest (bi-bk) tiles launch first.
// ============================================================
__global__ void __launch_bounds__(256, 2) su_fuse_mma(
    const __nv_bfloat16* __restrict__ T1H, const __nv_bfloat16* __restrict__ T1L,
    const __nv_bfloat16* __restrict__ LKH, const __nv_bfloat16* __restrict__ LKL,
    float* __restrict__ SC)
{
    const int h = blockIdx.z;
    int idx = blockIdx.y * 16 + blockIdx.x;
    int bi = -1, bk = 0;
    for (int d = 15; d >= 0; d--) {
        const int cnt = 16 - d;
        if (idx < cnt) { bk = idx; bi = idx + d; break; }
        idx -= cnt;
    }
    if (bi < 0) return;

    extern __shared__ char sm[];
    const uint32_t smb = smem_u32(sm);
    const int t = threadIdx.x;
    const int wid = t >> 5, lane = t & 31;
    const int m0 = (wid & 1) * 64;
    const int n0 = (wid >> 1) * 32;

    const size_t hb = (size_t)h * NS * NS;
    const __nv_bfloat16* srcs[4] = {
        T1H + hb + (size_t)(bi * 128) * NS,
        T1L + hb + (size_t)(bi * 128) * NS,
        LKH + hb + (size_t)(bk * 128) * NS,
        LKL + hb + (size_t)(bk * 128) * NS
    };

    const int grp  = t >> 6;
    const int gg   = t & 63;
    const int col  = gg & 3;
    const int row0 = gg >> 2;
    const __nv_bfloat16* gsrc = srcs[grp] + (size_t)row0 * NS + (size_t)bk * 128 + col * 8;
    const uint32_t sdst = smb + grp * TILEB + row0 * PADB + col * 16;

    const int nCh = 4 * (bi - bk + 1);
    ISSUE_128(0, gsrc, NS, sdst);

    float acc[4][4][4] = {};
    const int lrow = lane & 15;
    const uint32_t lkoff = (uint32_t)((lane >> 4) * 16);

    for (int c = 0; c < nCh; c++) {
        CP_WAIT0();
        __syncthreads();
        if (c + 1 < nCh) ISSUE_128(c + 1, gsrc, NS, sdst);
        const uint32_t bse = smb + (c & 1) * BUFB;
        mma_chunk_128(bse, bse + TILEB, bse + 2 * TILEB, bse + 3 * TILEB,
                      m0, n0, lrow, lkoff, acc);
    }

    const int g  = lane >> 2;
    const int tg = lane & 3;
#pragma unroll
    for (int tm = 0; tm < 4; tm++) {
#pragma unroll
        for (int tn = 0; tn < 4; tn++) {
            const int i0 = bi * 128 + m0 + tm * 16 + g;
            const int j0 = bk * 128 + n0 + tn * 8 + tg * 2;
            float* p0 = SC + hb + (size_t)i0 * NS + j0;
            float* p1 = p0 + (size_t)8 * NS;
            float2 c0 = *(float2*)p0;
            float2 c1 = *(float2*)p1;
            c0.x -= fast_silu(acc[tm][tn][0]);
            c0.y -= fast_silu(acc[tm][tn][1]);
            c1.x -= fast_silu(acc[tm][tn][2]);
            c1.y -= fast_silu(acc[tm][tn][3]);
            *(float2*)p0 = c0;
            *(float2*)p1 = c1;
        }
    }
}

// ============================================================
// Row softmax -> split bf16 attn
// ============================================================
__global__ void row_softmax_bf(const float* __restrict__ SC,
                               __nv_bfloat16* __restrict__ AH,
                               __nv_bfloat16* __restrict__ AL) {
    const int h = blockIdx.y, i = blockIdx.x;
    const float* row = SC + (size_t)h * NS * NS + (size_t)i * NS;
    __nv_bfloat16* rh = AH + (size_t)h * NS * NS + (size_t)i * NS;
    __nv_bfloat16* rl = AL + (size_t)h * NS * NS + (size_t)i * NS;
    const int t = threadIdx.x;
    const int len = i + 1;

    __shared__ float red[256];

    float lmax = -1e30f;
#pragma unroll
    for (int q = 0; q < 8; q++) {
        int j = t + q * 256;
        if (j < len) lmax = fmaxf(lmax, row[j]);
    }
    red[t] = lmax; __syncthreads();
    for (int s = 128; s > 0; s >>= 1) { if (t < s) red[t] = fmaxf(red[t], red[t + s]); __syncthreads(); }
    const float bmax = red[0];
    __syncthreads();

    float ev[8];
    float lsum = 0.0f;
#pragma unroll
    for (int q = 0; q < 8; q++) {
        int j = t + q * 256;
        float e = 0.0f;
        if (j < len) e = __expf(row[j] - bmax);
        ev[q] = e;
        lsum += e;
    }
    red[t] = lsum; __syncthreads();
    for (int s = 128; s > 0; s >>= 1) { if (t < s) red[t] += red[t + s]; __syncthreads(); }
    const float inv = __fdividef(1.0f, red[0]);

#pragma unroll
    for (int q = 0; q < 8; q++) {
        int j = t + q * 256;
        if (j < len) {
            float p = ev[q] * inv;
            __nv_bfloat16 hh; float r;
            split1(p, hh, r);
            rh[j] = hh;
            rl[j] = __float2bfloat16_rn(r);
        }
    }
    const int padEnd = ((i >> 7) + 1) << 7;
    const __nv_bfloat16 z = __float2bfloat16_rn(0.0f);
    for (int j = len + t; j < padEnd; j += 256) { rh[j] = z; rl[j] = z; }
}

// ============================================================
// AV: ctx = attn @ vc. 128x64 tiles, 2-stage, 3 CTAs/SM.
// ============================================================
__global__ void __launch_bounds__(256, 3) av_mma(
    const __nv_bfloat16* __restrict__ ATH, const __nv_bfloat16* __restrict__ ATL,
    const __nv_bfloat16* __restrict__ VTH, const __nv_bfloat16* __restrict__ VTL,
    __nv_bfloat16* __restrict__ CTH, __nv_bfloat16* __restrict__ CTL)
{
    const int h = blockIdx.y, bi = blockIdx.x;
    extern __shared__ char sm[];
    const uint32_t smb = smem_u32(sm);
    const int t = threadIdx.x;
    const int wid = t >> 5, lane = t & 31;
    const int m0 = (wid & 3) * 32;
    const int n0 = (wid >> 2) * 32;

    const size_t hb = (size_t)h * NS * NS;
    const __nv_bfloat16* gAh = ATH + hb + (size_t)(bi * 128) * NS;
    const __nv_bfloat16* gAl = ATL + hb + (size_t)(bi * 128) * NS;
    const __nv_bfloat16* gBh = VTH + (size_t)(h * DH) * NS;
    const __nv_bfloat16* gBl = VTL + (size_t)(h * DH) * NS;

    const int arow = t >> 1;
    const int ac0  = (t & 1) * 2;
    const int brow = t >> 2;
    const int bc0  = t & 3;

#define AV_ISSUE(c)                                                             \
    do {                                                                        \
        const size_t j0 = (size_t)(c) * 32;                                     \
        const uint32_t bb = smb + ((c) & 1) * AV_STAGE;                         \
        const __nv_bfloat16* pah = gAh + (size_t)arow * NS + j0 + ac0 * 8;      \
        const __nv_bfloat16* pal = gAl + (size_t)arow * NS + j0 + ac0 * 8;      \
        const uint32_t sA = bb + arow * PADB + ac0 * 16;                        \
        CPASYNC16(sA,                        pah);                              \
        CPASYNC16(sA + 16,                   pah + 8);                          \
        CPASYNC16(sA + 128 * PADB,           pal);                              \
        CPASYNC16(sA + 128 * PADB + 16,      pal + 8);                          \
        const __nv_bfloat16* pbh = gBh + (size_t)brow * NS + j0 + bc0 * 8;      \
        const __nv_bfloat16* pbl = gBl + (size_t)brow * NS + j0 + bc0 * 8;      \
        const uint32_t sB = bb + 256 * PADB + brow * PADB + bc0 * 16;           \
        CPASYNC16(sB,             pbh);                                         \
        CPASYNC16(sB + 64 * PADB, pbl);                                         \
        CP_COMMIT();                                                            \
    } while (0)

    const int nCh = 4 * (bi + 1);
    AV_ISSUE(0);

    float acc[2][4][4] = {};
    const int lrow = lane & 15;
    const uint32_t lkoff = (uint32_t)((lane >> 4) * 16);

    for (int c = 0; c < nCh; c++) {
        CP_WAIT0();
        __syncthreads();
        if (c + 1 < nCh) AV_ISSUE(c + 1);

        const uint32_t bse = smb + (c & 1) * AV_STAGE;
        mma_chunk_64(bse, bse + 128 * PADB, bse + 256 * PADB, bse + 320 * PADB,
                     m0, n0, lrow, lkoff, acc);
    }

    const int g  = lane >> 2;
    const int tg = lane & 3;
#pragma unroll
    for (int tm = 0; tm < 2; tm++) {
#pragma unroll
        for (int tn = 0; tn < 4; tn++) {
            const int i0 = bi * 128 + m0 + tm * 16 + g;
            const int d0 = n0 + tn * 8 + tg * 2;
            size_t o0 = (size_t)i0 * DIMM + h * DH + d0;
            size_t o1 = o0 + (size_t)8 * DIMM;
            float v0 = acc[tm][tn][0], v1 = acc[tm][tn][1];
            float v2 = acc[tm][tn][2], v3 = acc[tm][tn][3];
            __nv_bfloat16 hh; float r0, r1, r2, r3;
            split1(v0, hh, r0); split1(v1, hh, r1); split1(v2, hh, r2); split1(v3, hh, r3);
            *(uint32_t*)(CTH + o0) = pack_bf2(v0, v1);
            *(uint32_t*)(CTH + o1) = pack_bf2(v2, v3);
            *(uint32_t*)(CTL + o0) = pack_bf2(r0, r1);
            *(uint32_t*)(CTL + o1) = pack_bf2(r2, r3);
        }
    }
}

// ============================================================
// out = ctx @ Wout. 128x64 tiles, 2-stage, 3 CTAs/SM.
// ============================================================
__global__ void __launch_bounds__(256, 3) out_mma(
    const __nv_bfloat16* __restrict__ AH0, const __nv_bfloat16* __restrict__ AL0,
    const __nv_bfloat16* __restrict__ BH0, const __nv_bfloat16* __restrict__ BL0,
    float* __restrict__ C)
{
    const int bm = blockIdx.y, bn = blockIdx.x;
    extern __shared__ char sm[];
    const uint32_t smb = smem_u32(sm);
    const int t = threadIdx.x;
    const int wid = t >> 5, lane = t & 31;
    const int m0 = (wid & 3) * 32;
    const int n0 = (wid >> 2) * 32;

    const __nv_bfloat16* gAh = AH0 + (size_t)(bm * 128) * DIMM;
    const __nv_bfloat16* gAl = AL0 + (size_t)(bm * 128) * DIMM;
    const __nv_bfloat16* gBh = BH0 + (size_t)(bn * 64) * DIMM;
    const __nv_bfloat16* gBl = BL0 + (size_t)(bn * 64) * DIMM;

    const int arow = t >> 1;
    const int ac0  = (t & 1) * 2;
    const int brow = t >> 2;
    const int bc0  = t & 3;

#define OUT_ISSUE(c)                                                            \
    do {                                                                        \
        const size_t j0 = (size_t)(c) * 32;                                     \
        const uint32_t bb = smb + ((c) & 1) * AV_STAGE;                         \
        const __nv_bfloat16* pah = gAh + (size_t)arow * DIMM + j0 + ac0 * 8;    \
        const __nv_bfloat16* pal = gAl + (size_t)arow * DIMM + j0 + ac0 * 8;    \
        const uint32_t sA = bb + arow * PADB + ac0 * 16;                        \
        CPASYNC16(sA,                        pah);                              \
        CPASYNC16(sA + 16,                   pah + 8);                          \
        CPASYNC16(sA + 128 * PADB,           pal);                              \
        CPASYNC16(sA + 128 * PADB + 16,      pal + 8);                          \
        const __nv_bfloat16* pbh = gBh + (size_t)brow * DIMM + j0 + bc0 * 8;    \
        const __nv_bfloat16* pbl = gBl + (size_t)brow * DIMM + j0 + bc0 * 8;    \
        const uint32_t sB = bb + 256 * PADB + brow * PADB + bc0 * 16;           \
        CPASYNC16(sB,             pbh);                                         \
        CPASYNC16(sB + 64 * PADB, pbl);                                         \
        CP_COMMIT();                                                            \
    } while (0)

    OUT_ISSUE(0);

    float acc[2][4][4] = {};
    const int lrow = lane & 15;
    const uint32_t lkoff = (uint32_t)((lane >> 4) * 16);

    for (int c = 0; c < 32; c++) {
        CP_WAIT0();
        __syncthreads();
        if (c + 1 < 32) OUT_ISSUE(c + 1);

        const uint32_t bse = smb + (c & 1) * AV_STAGE;
        mma_chunk_64(bse, bse + 128 * PADB, bse + 256 * PADB, bse + 320 * PADB,
                     m0, n0, lrow, lkoff, acc);
    }

    const int g  = lane >> 2;
    const int tg = lane & 3;
#pragma unroll
    for (int tm = 0; tm < 2; tm++) {
#pragma unroll
        for (int tn = 0; tn < 4; tn++) {
            const int i0 = bm * 128 + m0 + tm * 16 + g;
            const int j0 = bn * 64 + n0 + tn * 8 + tg * 2;
            size_t o0 = (size_t)i0 * DIMM + j0;
            size_t o1 = o0 + (size_t)8 * DIMM;
            *(float2*)(C + o0) = make_float2(acc[tm][tn][0], acc[tm][tn][1]);
            *(float2*)(C + o1) = make_float2(acc[tm][tn][2], acc[tm][tn][3]);
        }
    }
}

// ============================================================
extern "C" void kernel_launch(void* const* d_in, const int* in_sizes, int n_in,
                              void* d_out, int out_size) {
    const float* x    = (const float*)d_in[0];
    const float* Wqkv = (const float*)d_in[1];
    const float* Wout = (const float*)d_in[2];
    float* out = (float*)d_out;

    float *sc;
    __nv_bfloat16 *qh, *ql, *xh, *xl, *wqh, *wql, *t1h, *t1l, *lkh, *lkl;
    __nv_bfloat16 *vth, *vtl, *cth, *ctl, *woh, *wol;
    cudaGetSymbolAddress((void**)&qh,  g_qh);
    cudaGetSymbolAddress((void**)&ql,  g_ql);
    cudaGetSymbolAddress((void**)&xh,  g_xh);
    cudaGetSymbolAddress((void**)&xl,  g_xl);
    cudaGetSymbolAddress((void**)&wqh, g_wqh);
    cudaGetSymbolAddress((void**)&wql, g_wql);
    cudaGetSymbolAddress((void**)&t1h, g_t1h);
    cudaGetSymbolAddress((void**)&t1l, g_t1l);
    cudaGetSymbolAddress((void**)&lkh, g_lkh);
    cudaGetSymbolAddress((void**)&lkl, g_lkl);
    cudaGetSymbolAddress((void**)&sc,  g_sc);
    cudaGetSymbolAddress((void**)&vth, g_vth);
    cudaGetSymbolAddress((void**)&vtl, g_vtl);
    cudaGetSymbolAddress((void**)&cth, g_cth);
    cudaGetSymbolAddress((void**)&ctl, g_ctl);
    cudaGetSymbolAddress((void**)&woh, g_woh);
    cudaGetSymbolAddress((void**)&wol, g_wol);

    cudaFuncSetAttribute(qkv_mma,     cudaFuncAttributeMaxDynamicSharedMemorySize, QK_SMEM);
    cudaFuncSetAttribute(su_fuse_mma, cudaFuncAttributeMaxDynamicSharedMemorySize, DBUF_SMEM);
    cudaFuncSetAttribute(out_mma,     cudaFuncAttributeMaxDynamicSharedMemorySize, AV_SMEM2);
    cudaFuncSetAttribute(av_mma,      cudaFuncAttributeMaxDynamicSharedMemorySize, AV_SMEM2);
    cudaFuncSetAttribute(head13_mma,  cudaFuncAttributeMaxDynamicSharedMemorySize, H13_SMEM);
    cudaFuncSetAttribute(head2_mma,   cudaFuncAttributeMaxDynamicSharedMemorySize, DBUF_SMEM);

    const dim3 thr(256);

    // 0) split inputs
    conv_split  <<<(NS * DIMM + 255) / 256, thr>>>(x, xh, xl, NS * DIMM);
    conv_split_T<<<dim3(LDQ / 32, DIMM / 32), dim3(32, 8)>>>(Wqkv, wqh, wql, DIMM, LDQ);
    conv_split_T<<<dim3(DIMM / 32, DIMM / 32), dim3(32, 8)>>>(Wout, woh, wol, DIMM, DIMM);

    // 1) qkv projection (64x128 tiles, 3 CTAs/SM)
    qkv_mma<<<dim3(LDQ / 128, NS / 64), thr, QK_SMEM>>>(xh, xl, wqh, wql, qh, ql);

    // 1b) vc^T split
    conv_vT<<<dim3(NS / 32, DH / 32, NH), dim3(32, 8)>>>(qh, ql, vth, vtl);

    // 2) per-head K=64 GEMMs: merged term1+Sc, separate lookahead
    const dim3 gHead(NS / 128, NS / 128, NH);
    head13_mma<<<gHead, thr, H13_SMEM>>>(qh, ql, t1h, t1l, sc);
    head2_mma <<<gHead, thr, DBUF_SMEM>>>(qh, ql, lkh, lkl);

    // 3) Su (work-descending order), fused scores = Sc - silu(Su)
    su_fuse_mma<<<gHead, thr, DBUF_SMEM>>>(t1h, t1l, lkh, lkl, sc);

    // 4) softmax -> attn split bf16 (reuses t1h/t1l)
    row_softmax_bf<<<dim3(NS, NH), thr>>>(sc, t1h, t1l);

    // 5) ctx = attn @ vc
    av_mma<<<dim3(NS / 128, NH), thr, AV_SMEM2>>>(t1h, t1l, vth, vtl, cth, ctl);

    // 6) out = ctx @ W_out
    out_mma<<<dim3(DIMM / 64, NS / 128), thr, AV_SMEM2>>>(cth, ctl, woh, wol, out);
}

// round 16
// speedup vs baseline: 1.0116x; 1.0116x over previous
#include <cuda_runtime.h>
#include <cuda_bf16.h>
#include <math.h>
#include <stdint.h>

#define NS   2048
#define NH   16
#define DH   64
#define DIMM 1024
#define LDQ  6144

__device__ __constant__ float SCALE = 0.125f;

// ---- scratch ----
__device__ __nv_bfloat16 g_qh [(size_t)NS * LDQ];
__device__ __nv_bfloat16 g_ql [(size_t)NS * LDQ];
__device__ __nv_bfloat16 g_xh [(size_t)NS * DIMM];
__device__ __nv_bfloat16 g_xl [(size_t)NS * DIMM];
__device__ __nv_bfloat16 g_wqh[(size_t)LDQ * DIMM];
__device__ __nv_bfloat16 g_wql[(size_t)LDQ * DIMM];
__device__ __nv_bfloat16 g_t1h[(size_t)NH * NS * NS];
__device__ __nv_bfloat16 g_t1l[(size_t)NH * NS * NS];
__device__ __nv_bfloat16 g_lkh[(size_t)NH * NS * NS];
__device__ __nv_bfloat16 g_lkl[(size_t)NH * NS * NS];
__device__ float g_sc [(size_t)NH * NS * NS];
__device__ __nv_bfloat16 g_vth[(size_t)NH * DH * NS];
__device__ __nv_bfloat16 g_vtl[(size_t)NH * DH * NS];
__device__ __nv_bfloat16 g_cth[(size_t)NS * DIMM];
__device__ __nv_bfloat16 g_ctl[(size_t)NS * DIMM];
__device__ __nv_bfloat16 g_woh[(size_t)DIMM * DIMM];
__device__ __nv_bfloat16 g_wol[(size_t)DIMM * DIMM];

// ============================================================
// helpers
// ============================================================
__device__ __forceinline__ uint32_t smem_u32(const void* p) {
    uint32_t a;
    asm("{ .reg .u64 t; cvta.to.shared.u64 t, %1; cvt.u32.u64 %0, t; }" : "=r"(a) : "l"(p));
    return a;
}

#define CPASYNC16(s, g) \
    asm volatile("cp.async.cg.shared.global [%0], [%1], 16;" :: "r"(s), "l"(g) : "memory")
#define CP_COMMIT() asm volatile("cp.async.commit_group;" ::: "memory")
#define CP_WAIT0()  asm volatile("cp.async.wait_group 0;" ::: "memory")
#define CP_WAIT1()  asm volatile("cp.async.wait_group 1;" ::: "memory")

#define LDMX4(r, addr) \
    asm volatile("ldmatrix.sync.aligned.m8n8.x4.shared.b16 {%0,%1,%2,%3}, [%4];" \
        : "=r"((r)[0]), "=r"((r)[1]), "=r"((r)[2]), "=r"((r)[3]) : "r"(addr))

#define MMA16816(d, a, b0, b1) \
    asm("mma.sync.aligned.m16n8k16.row.col.f32.bf16.bf16.f32 " \
        "{%0,%1,%2,%3}, {%4,%5,%6,%7}, {%8,%9}, {%0,%1,%2,%3};" \
        : "+f"((d)[0]), "+f"((d)[1]), "+f"((d)[2]), "+f"((d)[3]) \
        : "r"((a)[0]), "r"((a)[1]), "r"((a)[2]), "r"((a)[3]), "r"(b0), "r"(b1))

__device__ __forceinline__ uint32_t pack_bf2(float a, float b) {
    __nv_bfloat162 t = __floats2bfloat162_rn(a, b);
    return *(uint32_t*)&t;
}
__device__ __forceinline__ void split1(float v, __nv_bfloat16& h, float& r) {
    h = __float2bfloat16_rn(v);
    r = v - __bfloat162float(h);
}
__device__ __forceinline__ float fast_sigmoid(float x) {
    return __fdividef(1.0f, 1.0f + __expf(-x));
}
__device__ __forceinline__ float fast_silu(float x) {
    return __fdividef(x, 1.0f + __expf(-x));
}

// 32-wide K chunks: 64B data + 16B pad per row
#define PADB   80
#define TILEB  (128 * PADB)      // 10240
#define BUFB   (4 * TILEB)       // 40960
#define DBUF_SMEM (2 * BUFB)     // 81920 -> 2 CTAs/SM
#define AV_STAGE  (384 * PADB)   // 30720
#define AV_SMEM2  (2 * AV_STAGE) // 61440 -> 3 CTAs/SM

// qkv: 64x128 CTA tile, 3 CTAs/SM
#define QK_AH   0
#define QK_AL   (64 * PADB)
#define QK_BH   (2 * 64 * PADB)
#define QK_BL   (QK_BH + 128 * PADB)
#define QK_STAGE (QK_BH + 2 * 128 * PADB)  // 30720
#define QK_SMEM  (2 * QK_STAGE)            // 61440 -> 3 CTAs/SM

// ============================================================
// chunk compute: 128x128 tile, warp 64x32, K=32 per chunk (3 passes)
// ============================================================
__device__ __forceinline__ void mma_chunk_128(
    uint32_t aH, uint32_t aL, uint32_t bH, uint32_t bL,
    int m0, int n0, int lrow, uint32_t lkoff, float acc[4][4][4])
{
#pragma unroll
    for (int kk = 0; kk < 2; kk++) {
        const uint32_t ko = kk * 32 + lkoff;
        uint32_t ah[4][4], al[4][4];
        const uint32_t aoff = (uint32_t)((m0 + lrow) * PADB) + ko;
#pragma unroll
        for (int tm = 0; tm < 4; tm++) {
            LDMX4(ah[tm], aH + aoff + tm * 16 * PADB);
            LDMX4(al[tm], aL + aoff + tm * 16 * PADB);
        }
        uint32_t bh[2][4], bl[2][4];
        const uint32_t boff = (uint32_t)((n0 + lrow) * PADB) + ko;
#pragma unroll
        for (int tp = 0; tp < 2; tp++) {
            LDMX4(bh[tp], bH + boff + tp * 16 * PADB);
            LDMX4(bl[tp], bL + boff + tp * 16 * PADB);
        }
#pragma unroll
        for (int tm = 0; tm < 4; tm++)
#pragma unroll
            for (int tn = 0; tn < 4; tn++) {
                const int tp = tn >> 1, sel = tn & 1;
                MMA16816(acc[tm][tn], ah[tm], bh[tp][sel], bh[tp][sel + 2]);
            }
#pragma unroll
        for (int tm = 0; tm < 4; tm++)
#pragma unroll
            for (int tn = 0; tn < 4; tn++) {
                const int tp = tn >> 1, sel = tn & 1;
                MMA16816(acc[tm][tn], ah[tm], bl[tp][sel], bl[tp][sel + 2]);
            }
#pragma unroll
        for (int tm = 0; tm < 4; tm++)
#pragma unroll
            for (int tn = 0; tn < 4; tn++) {
                const int tp = tn >> 1, sel = tn & 1;
                MMA16816(acc[tm][tn], al[tm], bh[tp][sel], bh[tp][sel + 2]);
            }
    }
}

#define ISSUE_128(c, gsrc, ld, sdst)                                      \
    do {                                                                  \
        const __nv_bfloat16* gp_ = (gsrc) + (size_t)(c) * 32;             \
        const uint32_t sb_ = (sdst) + ((c) & 1) * BUFB;                   \
        _Pragma("unroll")                                                 \
        for (int kq = 0; kq < 8; kq++)                                    \
            CPASYNC16(sb_ + kq * 16 * PADB, gp_ + (size_t)(kq * 16) * (ld)); \
        CP_COMMIT();                                                      \
    } while (0)

// warp tile 32x32 chunk compute
__device__ __forceinline__ void mma_chunk_64(
    uint32_t aH, uint32_t aL, uint32_t bH, uint32_t bL,
    int m0, int n0, int lrow, uint32_t lkoff, float acc[2][4][4])
{
#pragma unroll
    for (int kk = 0; kk < 2; kk++) {
        const uint32_t ko = kk * 32 + lkoff;
        uint32_t ah[2][4], al[2][4];
        const uint32_t aoff = (uint32_t)((m0 + lrow) * PADB) + ko;
#pragma unroll
        for (int tm = 0; tm < 2; tm++) {
            LDMX4(ah[tm], aH + aoff + tm * 16 * PADB);
            LDMX4(al[tm], aL + aoff + tm * 16 * PADB);
        }
        uint32_t bh[2][4], bl[2][4];
        const uint32_t boff = (uint32_t)((n0 + lrow) * PADB) + ko;
#pragma unroll
        for (int tp = 0; tp < 2; tp++) {
            LDMX4(bh[tp], bH + boff + tp * 16 * PADB);
            LDMX4(bl[tp], bL + boff + tp * 16 * PADB);
        }
#pragma unroll
        for (int tm = 0; tm < 2; tm++)
#pragma unroll
            for (int tn = 0; tn < 4; tn++) {
                const int tp = tn >> 1, sel = tn & 1;
                MMA16816(acc[tm][tn], ah[tm], bh[tp][sel], bh[tp][sel + 2]);
            }
#pragma unroll
        for (int tm = 0; tm < 2; tm++)
#pragma unroll
            for (int tn = 0; tn < 4; tn++) {
                const int tp = tn >> 1, sel = tn & 1;
                MMA16816(acc[tm][tn], ah[tm], bl[tp][sel], bl[tp][sel + 2]);
            }
#pragma unroll
        for (int tm = 0; tm < 2; tm++)
#pragma unroll
            for (int tn = 0; tn < 4; tn++) {
                const int tp = tn >> 1, sel = tn & 1;
                MMA16816(acc[tm][tn], al[tm], bh[tp][sel], bh[tp][sel + 2]);
            }
    }
}

// ============================================================
// conversion kernels
// ============================================================
__global__ void conv_split(const float* __restrict__ src,
                           __nv_bfloat16* __restrict__ hi, __nv_bfloat16* __restrict__ lo,
                           int n) {
    int i = blockIdx.x * 256 + threadIdx.x;
    if (i >= n) return;
    float v = src[i];
    __nv_bfloat16 h; float r;
    split1(v, h, r);
    hi[i] = h;
    lo[i] = __float2bfloat16_rn(r);
}

__global__ void conv_split_T(const float* __restrict__ src,
                             __nv_bfloat16* __restrict__ hi, __nv_bfloat16* __restrict__ lo,
                             int R, int C) {
    __shared__ float tile[32][33];
    const int bx = blockIdx.x * 32, by = blockIdx.y * 32;
    const int tx = threadIdx.x, ty = threadIdx.y;
#pragma unroll
    for (int i = 0; i < 32; i += 8)
        tile[ty + i][tx] = src[(size_t)(by + ty + i) * C + bx + tx];
    __syncthreads();
#pragma unroll
    for (int i = 0; i < 32; i += 8) {
        float v = tile[tx][ty + i];
        __nv_bfloat16 h; float r;
        split1(v, h, r);
        size_t o = (size_t)(bx + ty + i) * R + by + tx;
        hi[o] = h;
        lo[o] = __float2bfloat16_rn(r);
    }
}

__global__ void conv_vT(const __nv_bfloat16* __restrict__ QH,
                        const __nv_bfloat16* __restrict__ QL,
                        __nv_bfloat16* __restrict__ hi, __nv_bfloat16* __restrict__ lo) {
    __shared__ float tile[32][33];
    const int h = blockIdx.z;
    const int bx = blockIdx.x * 32;
    const int by = blockIdx.y * 32;
    const int tx = threadIdx.x, ty = threadIdx.y;
#pragma unroll
    for (int i = 0; i < 32; i += 8) {
        size_t o = (size_t)(bx + ty + i) * LDQ + 5 * 1024 + h * DH + by + tx;
        tile[ty + i][tx] = __bfloat162float(QH[o]) + __bfloat162float(QL[o]);
    }
    __syncthreads();
#pragma unroll
    for (int i = 0; i < 32; i += 8) {
        float v = tile[tx][ty + i];
        __nv_bfloat16 hh; float r;
        split1(v, hh, r);
        size_t o = (size_t)(h * DH + by + ty + i) * NS + bx + tx;
        hi[o] = hh;
        lo[o] = __float2bfloat16_rn(r);
    }
}

// ============================================================
// qkv = x @ Wqkv — 64x128 tiles, 3 CTAs/SM
// ============================================================
__global__ void __launch_bounds__(256, 3) qkv_mma(
    const __nv_bfloat16* __restrict__ XH, const __nv_bfloat16* __restrict__ XL,
    const __nv_bfloat16* __restrict__ WH, const __nv_bfloat16* __restrict__ WL,
    __nv_bfloat16* __restrict__ QH, __nv_bfloat16* __restrict__ QL)
{
    const int bm = blockIdx.y;
    const int bn = blockIdx.x;
    extern __shared__ char sm[];
    const uint32_t smb = smem_u32(sm);
    const int t = threadIdx.x;
    const int wid = t >> 5, lane = t & 31;
    const int m0 = (wid & 1) * 32;
    const int n0 = (wid >> 1) * 32;

    const int isB   = t >> 7;
    const int g     = t & 127;
    const int a_row = g >> 1;
    const int a_c0  = (g & 1) * 2;
    const int b_row = g >> 2;
    const int b_c0  = g & 3;

    const __nv_bfloat16* pAh = XH + (size_t)(bm * 64 + a_row) * DIMM + a_c0 * 8;
    const __nv_bfloat16* pAl = XL + (size_t)(bm * 64 + a_row) * DIMM + a_c0 * 8;
    const __nv_bfloat16* pBh = WH + (size_t)(bn * 128 + b_row) * DIMM + b_c0 * 8;
    const __nv_bfloat16* pBl = WL + (size_t)(bn * 128 + b_row) * DIMM + b_c0 * 8;
    const uint32_t sAh = smb + QK_AH + a_row * PADB + a_c0 * 16;
    const uint32_t sAl = smb + QK_AL + a_row * PADB + a_c0 * 16;
    const uint32_t sBh = smb + QK_BH + b_row * PADB + b_c0 * 16;
    const uint32_t sBl = smb + QK_BL + b_row * PADB + b_c0 * 16;

#define QK_ISSUE(c)                                                           \
    do {                                                                      \
        const size_t kofs = (size_t)(c) * 32;                                 \
        const uint32_t bb = ((c) & 1) * QK_STAGE;                             \
        if (!isB) {                                                           \
            CPASYNC16(sAh + bb,      pAh + kofs);                             \
            CPASYNC16(sAh + bb + 16, pAh + kofs + 8);                         \
            CPASYNC16(sAl + bb,      pAl + kofs);                             \
            CPASYNC16(sAl + bb + 16, pAl + kofs + 8);                         \
        } else {                                                              \
            _Pragma("unroll")                                                 \
            for (int q = 0; q < 4; q++) {                                     \
                CPASYNC16(sBh + bb + q * 32 * PADB,                           \
                          pBh + kofs + (size_t)(q * 32) * DIMM);              \
                CPASYNC16(sBl + bb + q * 32 * PADB,                           \
                          pBl + kofs + (size_t)(q * 32) * DIMM);              \
            }                                                                 \
        }                                                                     \
        CP_COMMIT();                                                          \
    } while (0)

    QK_ISSUE(0);

    float acc[2][4][4] = {};
    const int lrow = lane & 15;
    const uint32_t lkoff = (uint32_t)((lane >> 4) * 16);

    for (int c = 0; c < 32; c++) {
        CP_WAIT0();
        __syncthreads();
        if (c + 1 < 32) QK_ISSUE(c + 1);
        const uint32_t bb = smb + (c & 1) * QK_STAGE;
        mma_chunk_64(bb + QK_AH, bb + QK_AL, bb + QK_BH, bb + QK_BL,
                     m0, n0, lrow, lkoff, acc);
    }

    const int gq = lane >> 2;
    const int tg = lane & 3;
#pragma unroll
    for (int tm = 0; tm < 2; tm++) {
#pragma unroll
        for (int tn = 0; tn < 4; tn++) {
            const int i0 = bm * 64 + m0 + tm * 16 + gq;
            const int j0 = bn * 128 + n0 + tn * 8 + tg * 2;
            float v0 = acc[tm][tn][0], v1 = acc[tm][tn][1];
            float v2 = acc[tm][tn][2], v3 = acc[tm][tn][3];
            size_t o0 = (size_t)i0 * LDQ + j0;
            size_t o1 = o0 + (size_t)8 * LDQ;
            __nv_bfloat16 h; float r0, r1, r2, r3;
            split1(v0, h, r0); split1(v1, h, r1); split1(v2, h, r2); split1(v3, h, r3);
            *(uint32_t*)(QH + o0) = pack_bf2(v0, v1);
            *(uint32_t*)(QH + o1) = pack_bf2(v2, v3);
            *(uint32_t*)(QL + o0) = pack_bf2(r0, r1);
            *(uint32_t*)(QL + o1) = pack_bf2(r2, r3);
        }
    }
}

// ============================================================
// Per-head NT GEMM K=64 (128x128, 2 CTAs/SM)
// ============================================================
template <int MODE>
__global__ void __launch_bounds__(256, 2) head_mma(
    const __nv_bfloat16* __restrict__ QH, const __nv_bfloat16* __restrict__ QL,
    int aoff, int boff,
    __nv_bfloat16* __restrict__ CH, __nv_bfloat16* __restrict__ CL,
    float* __restrict__ CF)
{
    const int h  = blockIdx.z;
    const int bi = blockIdx.y, bj = blockIdx.x;
    if (MODE != 2 && bj > bi) return;
    if (MODE == 2 && bj < bi) return;

    extern __shared__ char sm[];
    const uint32_t smb = smem_u32(sm);
    const int t = threadIdx.x;
    const int wid = t >> 5, lane = t & 31;
    const int m0 = (wid & 1) * 64;
    const int n0 = (wid >> 1) * 32;

    const int grp  = t >> 6;
    const int gg   = t & 63;
    const int col  = gg & 3;
    const int row0 = gg >> 2;
    const __nv_bfloat16* base;
    if (grp == 0)      base = QH + (size_t)(bi * 128) * LDQ + aoff + h * DH;
    else if (grp == 1) base = QL + (size_t)(bi * 128) * LDQ + aoff + h * DH;
    else if (grp == 2) base = QH + (size_t)(bj * 128) * LDQ + boff + h * DH;
    else               base = QL + (size_t)(bj * 128) * LDQ + boff + h * DH;
    const __nv_bfloat16* gsrc = base + (size_t)row0 * LDQ + col * 8;
    const uint32_t sdst = smb + grp * TILEB + row0 * PADB + col * 16;

    ISSUE_128(0, gsrc, LDQ, sdst);
    ISSUE_128(1, gsrc, LDQ, sdst);

    float acc[4][4][4] = {};
    const int lrow = lane & 15;
    const uint32_t lkoff = (uint32_t)((lane >> 4) * 16);

    CP_WAIT1();
    __syncthreads();
    {
        const uint32_t bse = smb;
        mma_chunk_128(bse, bse + TILEB, bse + 2 * TILEB, bse + 3 * TILEB,
                      m0, n0, lrow, lkoff, acc);
    }
    CP_WAIT0();
    __syncthreads();
    {
        const uint32_t bse = smb + BUFB;
        mma_chunk_128(bse, bse + TILEB, bse + 2 * TILEB, bse + 3 * TILEB,
                      m0, n0, lrow, lkoff, acc);
    }

    const size_t hb = (size_t)h * NS * NS;
    const int g  = lane >> 2;
    const int tg = lane & 3;
#pragma unroll
    for (int tm = 0; tm < 4; tm++) {
#pragma unroll
        for (int tn = 0; tn < 4; tn++) {
            const int i0 = bi * 128 + m0 + tm * 16 + g;
            const int j0 = bj * 128 + n0 + tn * 8 + tg * 2;
            float v[4];
            v[0] = acc[tm][tn][0] * SCALE; v[1] = acc[tm][tn][1] * SCALE;
            v[2] = acc[tm][tn][2] * SCALE; v[3] = acc[tm][tn][3] * SCALE;
            const int ii[4] = {i0, i0, i0 + 8, i0 + 8};
            const int jj[4] = {j0, j0 + 1, j0, j0 + 1};
#pragma unroll
            for (int q = 0; q < 4; q++) {
                if (MODE == 1) v[q] = (jj[q] <= ii[q]) ? v[q] : 0.0f;
                if (MODE == 2) v[q] = (jj[q] >  ii[q]) ? fast_sigmoid(v[q]) : 0.0f;
            }
            size_t o0 = hb + (size_t)i0 * NS + j0;
            size_t o1 = o0 + (size_t)8 * NS;
            if (MODE == 3) {
                *(float2*)(CF + o0) = make_float2(v[0], v[1]);
                *(float2*)(CF + o1) = make_float2(v[2], v[3]);
            } else {
                __nv_bfloat16 hh; float r[4];
                split1(v[0], hh, r[0]); split1(v[1], hh, r[1]);
                split1(v[2], hh, r[2]); split1(v[3], hh, r[3]);
                *(uint32_t*)(CH + o0) = pack_bf2(v[0], v[1]);
                *(uint32_t*)(CH + o1) = pack_bf2(v[2], v[3]);
                *(uint32_t*)(CL + o0) = pack_bf2(r[0], r[1]);
                *(uint32_t*)(CL + o1) = pack_bf2(r[2], r[3]);
            }
        }
    }
}

// ============================================================
// Su (128x128, 2 CTAs/SM), fused SC -= silu(Su).
// Super-block CTA remap for L2 operand reuse.
// ============================================================
__global__ void __launch_bounds__(256, 2) su_fuse_mma(
    const __nv_bfloat16* __restrict__ T1H, const __nv_bfloat16* __restrict__ T1L,
    const __nv_bfloat16* __restrict__ LKH, const __nv_bfloat16* __restrict__ LKL,
    float* __restrict__ SC)
{
    const int h = blockIdx.z;
    const int tlin = blockIdx.y * 16 + blockIdx.x;
    const int sup = tlin >> 4, inr = tlin & 15;
    const int bi = ((sup >> 2) << 2) | (inr >> 2);
    const int bk = ((sup & 3) << 2) | (inr & 3);
    if (bk > bi) return;

    extern __shared__ char sm[];
    const uint32_t smb = smem_u32(sm);
    const int t = threadIdx.x;
    const int wid = t >> 5, lane = t & 31;
    const int m0 = (wid & 1) * 64;
    const int n0 = (wid >> 1) * 32;

    const size_t hb = (size_t)h * NS * NS;
    const __nv_bfloat16* srcs[4] = {
        T1H + hb + (size_t)(bi * 128) * NS,
        T1L + hb + (size_t)(bi * 128) * NS,
        LKH + hb + (size_t)(bk * 128) * NS,
        LKL + hb + (size_t)(bk * 128) * NS
    };

    const int grp  = t >> 6;
    const int gg   = t & 63;
    const int col  = gg & 3;
    const int row0 = gg >> 2;
    const __nv_bfloat16* gsrc = srcs[grp] + (size_t)row0 * NS + (size_t)bk * 128 + col * 8;
    const uint32_t sdst = smb + grp * TILEB + row0 * PADB + col * 16;

    const int nCh = 4 * (bi - bk + 1);
    ISSUE_128(0, gsrc, NS, sdst);

    float acc[4][4][4] = {};
    const int lrow = lane & 15;
    const uint32_t lkoff = (uint32_t)((lane >> 4) * 16);

    for (int c = 0; c < nCh; c++) {
        CP_WAIT0();
        __syncthreads();
        if (c + 1 < nCh) ISSUE_128(c + 1, gsrc, NS, sdst);
        const uint32_t bse = smb + (c & 1) * BUFB;
        mma_chunk_128(bse, bse + TILEB, bse + 2 * TILEB, bse + 3 * TILEB,
                      m0, n0, lrow, lkoff, acc);
    }

    const int g  = lane >> 2;
    const int tg = lane & 3;
#pragma unroll
    for (int tm = 0; tm < 4; tm++) {
#pragma unroll
        for (int tn = 0; tn < 4; tn++) {
            const int i0 = bi * 128 + m0 + tm * 16 + g;
            const int j0 = bk * 128 + n0 + tn * 8 + tg * 2;
            float* p0 = SC + hb + (size_t)i0 * NS + j0;
            float* p1 = p0 + (size_t)8 * NS;
            float2 c0 = *(float2*)p0;
            float2 c1 = *(float2*)p1;
            c0.x -= fast_silu(acc[tm][tn][0]);
            c0.y -= fast_silu(acc[tm][tn][1]);
            c1.x -= fast_silu(acc[tm][tn][2]);
            c1.y -= fast_silu(acc[tm][tn][3]);
            *(float2*)p0 = c0;
            *(float2*)p1 = c1;
        }
    }
}

// ============================================================
// Row softmax -> split bf16 attn (fixed-trip loops: ev[] in regs)
// ============================================================
__global__ void row_softmax_bf(const float* __restrict__ SC,
                               __nv_bfloat16* __restrict__ AH,
                               __nv_bfloat16* __restrict__ AL) {
    const int h = blockIdx.y, i = blockIdx.x;
    const float* row = SC + (size_t)h * NS * NS + (size_t)i * NS;
    __nv_bfloat16* rh = AH + (size_t)h * NS * NS + (size_t)i * NS;
    __nv_bfloat16* rl = AL + (size_t)h * NS * NS + (size_t)i * NS;
    const int t = threadIdx.x;
    const int len = i + 1;

    __shared__ float red[256];

    float lmax = -1e30f;
#pragma unroll
    for (int q = 0; q < 8; q++) {
        int j = t + q * 256;
        if (j < len) lmax = fmaxf(lmax, row[j]);
    }
    red[t] = lmax; __syncthreads();
    for (int s = 128; s > 0; s >>= 1) { if (t < s) red[t] = fmaxf(red[t], red[t + s]); __syncthreads(); }
    const float bmax = red[0];
    __syncthreads();

    float ev[8];
    float lsum = 0.0f;
#pragma unroll
    for (int q = 0; q < 8; q++) {
        int j = t + q * 256;
        float e = 0.0f;
        if (j < len) e = __expf(row[j] - bmax);
        ev[q] = e;
        lsum += e;
    }
    red[t] = lsum; __syncthreads();
    for (int s = 128; s > 0; s >>= 1) { if (t < s) red[t] += red[t + s]; __syncthreads(); }
    const float inv = __fdividef(1.0f, red[0]);

#pragma unroll
    for (int q = 0; q < 8; q++) {
        int j = t + q * 256;
        if (j < len) {
            float p = ev[q] * inv;
            __nv_bfloat16 hh; float r;
            split1(p, hh, r);
            rh[j] = hh;
            rl[j] = __float2bfloat16_rn(r);
        }
    }
    const int padEnd = ((i >> 7) + 1) << 7;
    const __nv_bfloat16 z = __float2bfloat16_rn(0.0f);
    for (int j = len + t; j < padEnd; j += 256) { rh[j] = z; rl[j] = z; }
}

// ============================================================
// AV: ctx = attn @ vc. 128x64 tiles, 2-stage, 3 CTAs/SM.
// ============================================================
__global__ void __launch_bounds__(256, 3) av_mma(
    const __nv_bfloat16* __restrict__ ATH, const __nv_bfloat16* __restrict__ ATL,
    const __nv_bfloat16* __restrict__ VTH, const __nv_bfloat16* __restrict__ VTL,
    __nv_bfloat16* __restrict__ CTH, __nv_bfloat16* __restrict__ CTL)
{
    const int h = blockIdx.y, bi = blockIdx.x;
    extern __shared__ char sm[];
    const uint32_t smb = smem_u32(sm);
    const int t = threadIdx.x;
    const int wid = t >> 5, lane = t & 31;
    const int m0 = (wid & 3) * 32;
    const int n0 = (wid >> 2) * 32;

    const size_t hb = (size_t)h * NS * NS;
    const __nv_bfloat16* gAh = ATH + hb + (size_t)(bi * 128) * NS;
    const __nv_bfloat16* gAl = ATL + hb + (size_t)(bi * 128) * NS;
    const __nv_bfloat16* gBh = VTH + (size_t)(h * DH) * NS;
    const __nv_bfloat16* gBl = VTL + (size_t)(h * DH) * NS;

    const int arow = t >> 1;
    const int ac0  = (t & 1) * 2;
    const int brow = t >> 2;
    const int bc0  = t & 3;

#define AV_ISSUE(c)                                                             \
    do {                                                                        \
        const size_t j0 = (size_t)(c) * 32;                                     \
        const uint32_t bb = smb + ((c) & 1) * AV_STAGE;                         \
        const __nv_bfloat16* pah = gAh + (size_t)arow * NS + j0 + ac0 * 8;      \
        const __nv_bfloat16* pal = gAl + (size_t)arow * NS + j0 + ac0 * 8;      \
        const uint32_t sA = bb + arow * PADB + ac0 * 16;                        \
        CPASYNC16(sA,                        pah);                              \
        CPASYNC16(sA + 16,                   pah + 8);                          \
        CPASYNC16(sA + 128 * PADB,           pal);                              \
        CPASYNC16(sA + 128 * PADB + 16,      pal + 8);                          \
        const __nv_bfloat16* pbh = gBh + (size_t)brow * NS + j0 + bc0 * 8;      \
        const __nv_bfloat16* pbl = gBl + (size_t)brow * NS + j0 + bc0 * 8;      \
        const uint32_t sB = bb + 256 * PADB + brow * PADB + bc0 * 16;           \
        CPASYNC16(sB,             pbh);                                         \
        CPASYNC16(sB + 64 * PADB, pbl);                                         \
        CP_COMMIT();                                                            \
    } while (0)

    const int nCh = 4 * (bi + 1);
    AV_ISSUE(0);

    float acc[2][4][4] = {};
    const int lrow = lane & 15;
    const uint32_t lkoff = (uint32_t)((lane >> 4) * 16);

    for (int c = 0; c < nCh; c++) {
        CP_WAIT0();
        __syncthreads();
        if (c + 1 < nCh) AV_ISSUE(c + 1);

        const uint32_t bse = smb + (c & 1) * AV_STAGE;
        mma_chunk_64(bse, bse + 128 * PADB, bse + 256 * PADB, bse + 320 * PADB,
                     m0, n0, lrow, lkoff, acc);
    }

    const int g  = lane >> 2;
    const int tg = lane & 3;
#pragma unroll
    for (int tm = 0; tm < 2; tm++) {
#pragma unroll
        for (int tn = 0; tn < 4; tn++) {
            const int i0 = bi * 128 + m0 + tm * 16 + g;
            const int d0 = n0 + tn * 8 + tg * 2;
            size_t o0 = (size_t)i0 * DIMM + h * DH + d0;
            size_t o1 = o0 + (size_t)8 * DIMM;
            float v0 = acc[tm][tn][0], v1 = acc[tm][tn][1];
            float v2 = acc[tm][tn][2], v3 = acc[tm][tn][3];
            __nv_bfloat16 hh; float r0, r1, r2, r3;
            split1(v0, hh, r0); split1(v1, hh, r1); split1(v2, hh, r2); split1(v3, hh, r3);
            *(uint32_t*)(CTH + o0) = pack_bf2(v0, v1);
            *(uint32_t*)(CTH + o1) = pack_bf2(v2, v3);
            *(uint32_t*)(CTL + o0) = pack_bf2(r0, r1);
            *(uint32_t*)(CTL + o1) = pack_bf2(r2, r3);
        }
    }
}

// ============================================================
// out = ctx @ Wout. 128x64 tiles, 2-stage, 3 CTAs/SM.
// ============================================================
__global__ void __launch_bounds__(256, 3) out_mma(
    const __nv_bfloat16* __restrict__ AH0, const __nv_bfloat16* __restrict__ AL0,
    const __nv_bfloat16* __restrict__ BH0, const __nv_bfloat16* __restrict__ BL0,
    float* __restrict__ C)
{
    const int bm = blockIdx.y, bn = blockIdx.x;
    extern __shared__ char sm[];
    const uint32_t smb = smem_u32(sm);
    const int t = threadIdx.x;
    const int wid = t >> 5, lane = t & 31;
    const int m0 = (wid & 3) * 32;
    const int n0 = (wid >> 2) * 32;

    const __nv_bfloat16* gAh = AH0 + (size_t)(bm * 128) * DIMM;
    const __nv_bfloat16* gAl = AL0 + (size_t)(bm * 128) * DIMM;
    const __nv_bfloat16* gBh = BH0 + (size_t)(bn * 64) * DIMM;
    const __nv_bfloat16* gBl = BL0 + (size_t)(bn * 64) * DIMM;

    const int arow = t >> 1;
    const int ac0  = (t & 1) * 2;
    const int brow = t >> 2;
    const int bc0  = t & 3;

#define OUT_ISSUE(c)                                                            \
    do {                                                                        \
        const size_t j0 = (size_t)(c) * 32;                                     \
        const uint32_t bb = smb + ((c) & 1) * AV_STAGE;                         \
        const __nv_bfloat16* pah = gAh + (size_t)arow * DIMM + j0 + ac0 * 8;    \
        const __nv_bfloat16* pal = gAl + (size_t)arow * DIMM + j0 + ac0 * 8;    \
        const uint32_t sA = bb + arow * PADB + ac0 * 16;                        \
        CPASYNC16(sA,                        pah);                              \
        CPASYNC16(sA + 16,                   pah + 8);                          \
        CPASYNC16(sA + 128 * PADB,           pal);                              \
        CPASYNC16(sA + 128 * PADB + 16,      pal + 8);                          \
        const __nv_bfloat16* pbh = gBh + (size_t)brow * DIMM + j0 + bc0 * 8;    \
        const __nv_bfloat16* pbl = gBl + (size_t)brow * DIMM + j0 + bc0 * 8;    \
        const uint32_t sB = bb + 256 * PADB + brow * PADB + bc0 * 16;           \
        CPASYNC16(sB,             pbh);                                         \
        CPASYNC16(sB + 64 * PADB, pbl);                                         \
        CP_COMMIT();                                                            \
    } while (0)

    OUT_ISSUE(0);

    float acc[2][4][4] = {};
    const int lrow = lane & 15;
    const uint32_t lkoff = (uint32_t)((lane >> 4) * 16);

    for (int c = 0; c < 32; c++) {
        CP_WAIT0();
        __syncthreads();
        if (c + 1 < 32) OUT_ISSUE(c + 1);

        const uint32_t bse = smb + (c & 1) * AV_STAGE;
        mma_chunk_64(bse, bse + 128 * PADB, bse + 256 * PADB, bse + 320 * PADB,
                     m0, n0, lrow, lkoff, acc);
    }

    const int g  = lane >> 2;
    const int tg = lane & 3;
#pragma unroll
    for (int tm = 0; tm < 2; tm++) {
#pragma unroll
        for (int tn = 0; tn < 4; tn++) {
            const int i0 = bm * 128 + m0 + tm * 16 + g;
            const int j0 = bn * 64 + n0 + tn * 8 + tg * 2;
            size_t o0 = (size_t)i0 * DIMM + j0;
            size_t o1 = o0 + (size_t)8 * DIMM;
            *(float2*)(C + o0) = make_float2(acc[tm][tn][0], acc[tm][tn][1]);
            *(float2*)(C + o1) = make_float2(acc[tm][tn][2], acc[tm][tn][3]);
        }
    }
}

// ============================================================
extern "C" void kernel_launch(void* const* d_in, const int* in_sizes, int n_in,
                              void* d_out, int out_size) {
    const float* x    = (const float*)d_in[0];
    const float* Wqkv = (const float*)d_in[1];
    const float* Wout = (const float*)d_in[2];
    float* out = (float*)d_out;

    float *sc;
    __nv_bfloat16 *qh, *ql, *xh, *xl, *wqh, *wql, *t1h, *t1l, *lkh, *lkl;
    __nv_bfloat16 *vth, *vtl, *cth, *ctl, *woh, *wol;
    cudaGetSymbolAddress((void**)&qh,  g_qh);
    cudaGetSymbolAddress((void**)&ql,  g_ql);
    cudaGetSymbolAddress((void**)&xh,  g_xh);
    cudaGetSymbolAddress((void**)&xl,  g_xl);
    cudaGetSymbolAddress((void**)&wqh, g_wqh);
    cudaGetSymbolAddress((void**)&wql, g_wql);
    cudaGetSymbolAddress((void**)&t1h, g_t1h);
    cudaGetSymbolAddress((void**)&t1l, g_t1l);
    cudaGetSymbolAddress((void**)&lkh, g_lkh);
    cudaGetSymbolAddress((void**)&lkl, g_lkl);
    cudaGetSymbolAddress((void**)&sc,  g_sc);
    cudaGetSymbolAddress((void**)&vth, g_vth);
    cudaGetSymbolAddress((void**)&vtl, g_vtl);
    cudaGetSymbolAddress((void**)&cth, g_cth);
    cudaGetSymbolAddress((void**)&ctl, g_ctl);
    cudaGetSymbolAddress((void**)&woh, g_woh);
    cudaGetSymbolAddress((void**)&wol, g_wol);

    cudaFuncSetAttribute(qkv_mma,     cudaFuncAttributeMaxDynamicSharedMemorySize, QK_SMEM);
    cudaFuncSetAttribute(su_fuse_mma, cudaFuncAttributeMaxDynamicSharedMemorySize, DBUF_SMEM);
    cudaFuncSetAttribute(out_mma,     cudaFuncAttributeMaxDynamicSharedMemorySize, AV_SMEM2);
    cudaFuncSetAttribute(av_mma,      cudaFuncAttributeMaxDynamicSharedMemorySize, AV_SMEM2);
    cudaFuncSetAttribute(head_mma<1>, cudaFuncAttributeMaxDynamicSharedMemorySize, DBUF_SMEM);
    cudaFuncSetAttribute(head_mma<2>, cudaFuncAttributeMaxDynamicSharedMemorySize, DBUF_SMEM);
    cudaFuncSetAttribute(head_mma<3>, cudaFuncAttributeMaxDynamicSharedMemorySize, DBUF_SMEM);

    const dim3 thr(256);

    // 0) split inputs
    conv_split  <<<(NS * DIMM + 255) / 256, thr>>>(x, xh, xl, NS * DIMM);
    conv_split_T<<<dim3(LDQ / 32, DIMM / 32), dim3(32, 8)>>>(Wqkv, wqh, wql, DIMM, LDQ);
    conv_split_T<<<dim3(DIMM / 32, DIMM / 32), dim3(32, 8)>>>(Wout, woh, wol, DIMM, DIMM);

    // 1) qkv projection (64x128 tiles, 3 CTAs/SM)
    qkv_mma<<<dim3(LDQ / 128, NS / 64), thr, QK_SMEM>>>(xh, xl, wqh, wql, qh, ql);

    // 1b) vc^T split
    conv_vT<<<dim3(NS / 32, DH / 32, NH), dim3(32, 8)>>>(qh, ql, vth, vtl);

    // 2) per-head K=64 GEMMs (128x128 tiles)
    const dim3 gHead(NS / 128, NS / 128, NH);
    head_mma<1><<<gHead, thr, DBUF_SMEM>>>(qh, ql, 3 * 1024, 2 * 1024, t1h, t1l, nullptr);
    head_mma<2><<<gHead, thr, DBUF_SMEM>>>(qh, ql, 0 * 1024, 1 * 1024, lkh, lkl, nullptr);
    head_mma<3><<<gHead, thr, DBUF_SMEM>>>(qh, ql, 3 * 1024, 4 * 1024, nullptr, nullptr, sc);

    // 3) Su (super-block scheduled), fused scores = Sc - silu(Su)
    su_fuse_mma<<<gHead, thr, DBUF_SMEM>>>(t1h, t1l, lkh, lkl, sc);

    // 4) softmax -> attn split bf16 (reuses t1h/t1l)
    row_softmax_bf<<<dim3(NS, NH), thr>>>(sc, t1h, t1l);

    // 5) ctx = attn @ vc
    av_mma<<<dim3(NS / 128, NH), thr, AV_SMEM2>>>(t1h, t1l, vth, vtl, cth, ctl);

    // 6) out = ctx @ W_out
    out_mma<<<dim3(DIMM / 64, NS / 128), thr, AV_SMEM2>>>(cth, ctl, woh, wol, out);
}

// round 17
// speedup vs baseline: 1.0193x; 1.0076x over previous
#include <cuda_runtime.h>
#include <cuda_bf16.h>
#include <math.h>
#include <stdint.h>

#define NS   2048
#define NH   16
#define DH   64
#define DIMM 1024
#define LDQ  6144

__device__ __constant__ float SCALE = 0.125f;

// ---- scratch ----
__device__ __nv_bfloat16 g_qh [(size_t)NS * LDQ];
__device__ __nv_bfloat16 g_ql [(size_t)NS * LDQ];
__device__ __nv_bfloat16 g_xh [(size_t)NS * DIMM];
__device__ __nv_bfloat16 g_xl [(size_t)NS * DIMM];
__device__ __nv_bfloat16 g_wqh[(size_t)LDQ * DIMM];
__device__ __nv_bfloat16 g_wql[(size_t)LDQ * DIMM];
__device__ __nv_bfloat16 g_t1h[(size_t)NH * NS * NS];
__device__ __nv_bfloat16 g_t1l[(size_t)NH * NS * NS];
__device__ __nv_bfloat16 g_lkh[(size_t)NH * NS * NS];
__device__ __nv_bfloat16 g_lkl[(size_t)NH * NS * NS];
__device__ float g_sc [(size_t)NH * NS * NS];
__device__ __nv_bfloat16 g_vth[(size_t)NH * DH * NS];
__device__ __nv_bfloat16 g_vtl[(size_t)NH * DH * NS];
__device__ __nv_bfloat16 g_cth[(size_t)NS * DIMM];
__device__ __nv_bfloat16 g_ctl[(size_t)NS * DIMM];
__device__ __nv_bfloat16 g_woh[(size_t)DIMM * DIMM];
__device__ __nv_bfloat16 g_wol[(size_t)DIMM * DIMM];

// ============================================================
// helpers
// ============================================================
__device__ __forceinline__ uint32_t smem_u32(const void* p) {
    uint32_t a;
    asm("{ .reg .u64 t; cvta.to.shared.u64 t, %1; cvt.u32.u64 %0, t; }" : "=r"(a) : "l"(p));
    return a;
}

#define CPASYNC16(s, g) \
    asm volatile("cp.async.cg.shared.global [%0], [%1], 16;" :: "r"(s), "l"(g) : "memory")
#define CP_COMMIT() asm volatile("cp.async.commit_group;" ::: "memory")
#define CP_WAIT0()  asm volatile("cp.async.wait_group 0;" ::: "memory")
#define CP_WAIT1()  asm volatile("cp.async.wait_group 1;" ::: "memory")

#define LDMX4(r, addr) \
    asm volatile("ldmatrix.sync.aligned.m8n8.x4.shared.b16 {%0,%1,%2,%3}, [%4];" \
        : "=r"((r)[0]), "=r"((r)[1]), "=r"((r)[2]), "=r"((r)[3]) : "r"(addr))

#define MMA16816(d, a, b0, b1) \
    asm("mma.sync.aligned.m16n8k16.row.col.f32.bf16.bf16.f32 " \
        "{%0,%1,%2,%3}, {%4,%5,%6,%7}, {%8,%9}, {%0,%1,%2,%3};" \
        : "+f"((d)[0]), "+f"((d)[1]), "+f"((d)[2]), "+f"((d)[3]) \
        : "r"((a)[0]), "r"((a)[1]), "r"((a)[2]), "r"((a)[3]), "r"(b0), "r"(b1))

__device__ __forceinline__ uint32_t pack_bf2(float a, float b) {
    __nv_bfloat162 t = __floats2bfloat162_rn(a, b);
    return *(uint32_t*)&t;
}
__device__ __forceinline__ void split1(float v, __nv_bfloat16& h, float& r) {
    h = __float2bfloat16_rn(v);
    r = v - __bfloat162float(h);
}
__device__ __forceinline__ float fast_sigmoid(float x) {
    return __fdividef(1.0f, 1.0f + __expf(-x));
}
__device__ __forceinline__ float fast_silu(float x) {
    return __fdividef(x, 1.0f + __expf(-x));
}

// 32-wide K chunks: 64B data + 16B pad per row
#define PADB   80
#define TILEB  (128 * PADB)      // 10240
#define BUFB   (4 * TILEB)       // 40960
#define DBUF_SMEM (2 * BUFB)     // 81920 -> 2 CTAs/SM
#define AV_STAGE  (384 * PADB)   // 30720
#define AV_SMEM2  (2 * AV_STAGE) // 61440 -> 3 CTAs/SM

// qkv: 64x128 CTA tile, 3 CTAs/SM
#define QK_AH   0
#define QK_AL   (64 * PADB)
#define QK_BH   (2 * 64 * PADB)
#define QK_BL   (QK_BH + 128 * PADB)
#define QK_STAGE (QK_BH + 2 * 128 * PADB)  // 30720
#define QK_SMEM  (2 * QK_STAGE)            // 61440 -> 3 CTAs/SM

// ============================================================
// chunk compute: 128x128 tile, warp 64x32, K=32 per chunk (3 passes)
// ============================================================
__device__ __forceinline__ void mma_chunk_128(
    uint32_t aH, uint32_t aL, uint32_t bH, uint32_t bL,
    int m0, int n0, int lrow, uint32_t lkoff, float acc[4][4][4])
{
#pragma unroll
    for (int kk = 0; kk < 2; kk++) {
        const uint32_t ko = kk * 32 + lkoff;
        uint32_t ah[4][4], al[4][4];
        const uint32_t aoff = (uint32_t)((m0 + lrow) * PADB) + ko;
#pragma unroll
        for (int tm = 0; tm < 4; tm++) {
            LDMX4(ah[tm], aH + aoff + tm * 16 * PADB);
            LDMX4(al[tm], aL + aoff + tm * 16 * PADB);
        }
        uint32_t bh[2][4], bl[2][4];
        const uint32_t boff = (uint32_t)((n0 + lrow) * PADB) + ko;
#pragma unroll
        for (int tp = 0; tp < 2; tp++) {
            LDMX4(bh[tp], bH + boff + tp * 16 * PADB);
            LDMX4(bl[tp], bL + boff + tp * 16 * PADB);
        }
#pragma unroll
        for (int tm = 0; tm < 4; tm++)
#pragma unroll
            for (int tn = 0; tn < 4; tn++) {
                const int tp = tn >> 1, sel = tn & 1;
                MMA16816(acc[tm][tn], ah[tm], bh[tp][sel], bh[tp][sel + 2]);
            }
#pragma unroll
        for (int tm = 0; tm < 4; tm++)
#pragma unroll
            for (int tn = 0; tn < 4; tn++) {
                const int tp = tn >> 1, sel = tn & 1;
                MMA16816(acc[tm][tn], ah[tm], bl[tp][sel], bl[tp][sel + 2]);
            }
#pragma unroll
        for (int tm = 0; tm < 4; tm++)
#pragma unroll
            for (int tn = 0; tn < 4; tn++) {
                const int tp = tn >> 1, sel = tn & 1;
                MMA16816(acc[tm][tn], al[tm], bh[tp][sel], bh[tp][sel + 2]);
            }
    }
}

#define ISSUE_128(c, gsrc, ld, sdst)                                      \
    do {                                                                  \
        const __nv_bfloat16* gp_ = (gsrc) + (size_t)(c) * 32;             \
        const uint32_t sb_ = (sdst) + ((c) & 1) * BUFB;                   \
        _Pragma("unroll")                                                 \
        for (int kq = 0; kq < 8; kq++)                                    \
            CPASYNC16(sb_ + kq * 16 * PADB, gp_ + (size_t)(kq * 16) * (ld)); \
        CP_COMMIT();                                                      \
    } while (0)

// warp tile 32x32 chunk compute
__device__ __forceinline__ void mma_chunk_64(
    uint32_t aH, uint32_t aL, uint32_t bH, uint32_t bL,
    int m0, int n0, int lrow, uint32_t lkoff, float acc[2][4][4])
{
#pragma unroll
    for (int kk = 0; kk < 2; kk++) {
        const uint32_t ko = kk * 32 + lkoff;
        uint32_t ah[2][4], al[2][4];
        const uint32_t aoff = (uint32_t)((m0 + lrow) * PADB) + ko;
#pragma unroll
        for (int tm = 0; tm < 2; tm++) {
            LDMX4(ah[tm], aH + aoff + tm * 16 * PADB);
            LDMX4(al[tm], aL + aoff + tm * 16 * PADB);
        }
        uint32_t bh[2][4], bl[2][4];
        const uint32_t boff = (uint32_t)((n0 + lrow) * PADB) + ko;
#pragma unroll
        for (int tp = 0; tp < 2; tp++) {
            LDMX4(bh[tp], bH + boff + tp * 16 * PADB);
            LDMX4(bl[tp], bL + boff + tp * 16 * PADB);
        }
#pragma unroll
        for (int tm = 0; tm < 2; tm++)
#pragma unroll
            for (int tn = 0; tn < 4; tn++) {
                const int tp = tn >> 1, sel = tn & 1;
                MMA16816(acc[tm][tn], ah[tm], bh[tp][sel], bh[tp][sel + 2]);
            }
#pragma unroll
        for (int tm = 0; tm < 2; tm++)
#pragma unroll
            for (int tn = 0; tn < 4; tn++) {
                const int tp = tn >> 1, sel = tn & 1;
                MMA16816(acc[tm][tn], ah[tm], bl[tp][sel], bl[tp][sel + 2]);
            }
#pragma unroll
        for (int tm = 0; tm < 2; tm++)
#pragma unroll
            for (int tn = 0; tn < 4; tn++) {
                const int tp = tn >> 1, sel = tn & 1;
                MMA16816(acc[tm][tn], al[tm], bh[tp][sel], bh[tp][sel + 2]);
            }
    }
}

// ============================================================
// conversion kernels
// ============================================================
__global__ void conv_split(const float* __restrict__ src,
                           __nv_bfloat16* __restrict__ hi, __nv_bfloat16* __restrict__ lo,
                           int n) {
    int i = blockIdx.x * 256 + threadIdx.x;
    if (i >= n) return;
    float v = src[i];
    __nv_bfloat16 h; float r;
    split1(v, h, r);
    hi[i] = h;
    lo[i] = __float2bfloat16_rn(r);
}

__global__ void conv_split_T(const float* __restrict__ src,
                             __nv_bfloat16* __restrict__ hi, __nv_bfloat16* __restrict__ lo,
                             int R, int C) {
    __shared__ float tile[32][33];
    const int bx = blockIdx.x * 32, by = blockIdx.y * 32;
    const int tx = threadIdx.x, ty = threadIdx.y;
#pragma unroll
    for (int i = 0; i < 32; i += 8)
        tile[ty + i][tx] = src[(size_t)(by + ty + i) * C + bx + tx];
    __syncthreads();
#pragma unroll
    for (int i = 0; i < 32; i += 8) {
        float v = tile[tx][ty + i];
        __nv_bfloat16 h; float r;
        split1(v, h, r);
        size_t o = (size_t)(bx + ty + i) * R + by + tx;
        hi[o] = h;
        lo[o] = __float2bfloat16_rn(r);
    }
}

__global__ void conv_vT(const __nv_bfloat16* __restrict__ QH,
                        const __nv_bfloat16* __restrict__ QL,
                        __nv_bfloat16* __restrict__ hi, __nv_bfloat16* __restrict__ lo) {
    __shared__ float tile[32][33];
    const int h = blockIdx.z;
    const int bx = blockIdx.x * 32;
    const int by = blockIdx.y * 32;
    const int tx = threadIdx.x, ty = threadIdx.y;
#pragma unroll
    for (int i = 0; i < 32; i += 8) {
        size_t o = (size_t)(bx + ty + i) * LDQ + 5 * 1024 + h * DH + by + tx;
        tile[ty + i][tx] = __bfloat162float(QH[o]) + __bfloat162float(QL[o]);
    }
    __syncthreads();
#pragma unroll
    for (int i = 0; i < 32; i += 8) {
        float v = tile[tx][ty + i];
        __nv_bfloat16 hh; float r;
        split1(v, hh, r);
        size_t o = (size_t)(h * DH + by + ty + i) * NS + bx + tx;
        hi[o] = hh;
        lo[o] = __float2bfloat16_rn(r);
    }
}

// ============================================================
// qkv = x @ Wqkv — 64x128 tiles, 3 CTAs/SM
// ============================================================
__global__ void __launch_bounds__(256, 3) qkv_mma(
    const __nv_bfloat16* __restrict__ XH, const __nv_bfloat16* __restrict__ XL,
    const __nv_bfloat16* __restrict__ WH, const __nv_bfloat16* __restrict__ WL,
    __nv_bfloat16* __restrict__ QH, __nv_bfloat16* __restrict__ QL)
{
    const int bm = blockIdx.y;
    const int bn = blockIdx.x;
    extern __shared__ char sm[];
    const uint32_t smb = smem_u32(sm);
    const int t = threadIdx.x;
    const int wid = t >> 5, lane = t & 31;
    const int m0 = (wid & 1) * 32;
    const int n0 = (wid >> 1) * 32;

    const int isB   = t >> 7;
    const int g     = t & 127;
    const int a_row = g >> 1;
    const int a_c0  = (g & 1) * 2;
    const int b_row = g >> 2;
    const int b_c0  = g & 3;

    const __nv_bfloat16* pAh = XH + (size_t)(bm * 64 + a_row) * DIMM + a_c0 * 8;
    const __nv_bfloat16* pAl = XL + (size_t)(bm * 64 + a_row) * DIMM + a_c0 * 8;
    const __nv_bfloat16* pBh = WH + (size_t)(bn * 128 + b_row) * DIMM + b_c0 * 8;
    const __nv_bfloat16* pBl = WL + (size_t)(bn * 128 + b_row) * DIMM + b_c0 * 8;
    const uint32_t sAh = smb + QK_AH + a_row * PADB + a_c0 * 16;
    const uint32_t sAl = smb + QK_AL + a_row * PADB + a_c0 * 16;
    const uint32_t sBh = smb + QK_BH + b_row * PADB + b_c0 * 16;
    const uint32_t sBl = smb + QK_BL + b_row * PADB + b_c0 * 16;

#define QK_ISSUE(c)                                                           \
    do {                                                                      \
        const size_t kofs = (size_t)(c) * 32;                                 \
        const uint32_t bb = ((c) & 1) * QK_STAGE;                             \
        if (!isB) {                                                           \
            CPASYNC16(sAh + bb,      pAh + kofs);                             \
            CPASYNC16(sAh + bb + 16, pAh + kofs + 8);                         \
            CPASYNC16(sAl + bb,      pAl + kofs);                             \
            CPASYNC16(sAl + bb + 16, pAl + kofs + 8);                         \
        } else {                                                              \
            _Pragma("unroll")                                                 \
            for (int q = 0; q < 4; q++) {                                     \
                CPASYNC16(sBh + bb + q * 32 * PADB,                           \
                          pBh + kofs + (size_t)(q * 32) * DIMM);              \
                CPASYNC16(sBl + bb + q * 32 * PADB,                           \
                          pBl + kofs + (size_t)(q * 32) * DIMM);              \
            }                                                                 \
        }                                                                     \
        CP_COMMIT();                                                          \
    } while (0)

    QK_ISSUE(0);

    float acc[2][4][4] = {};
    const int lrow = lane & 15;
    const uint32_t lkoff = (uint32_t)((lane >> 4) * 16);

    for (int c = 0; c < 32; c++) {
        CP_WAIT0();
        __syncthreads();
        if (c + 1 < 32) QK_ISSUE(c + 1);
        const uint32_t bb = smb + (c & 1) * QK_STAGE;
        mma_chunk_64(bb + QK_AH, bb + QK_AL, bb + QK_BH, bb + QK_BL,
                     m0, n0, lrow, lkoff, acc);
    }

    const int gq = lane >> 2;
    const int tg = lane & 3;
#pragma unroll
    for (int tm = 0; tm < 2; tm++) {
#pragma unroll
        for (int tn = 0; tn < 4; tn++) {
            const int i0 = bm * 64 + m0 + tm * 16 + gq;
            const int j0 = bn * 128 + n0 + tn * 8 + tg * 2;
            float v0 = acc[tm][tn][0], v1 = acc[tm][tn][1];
            float v2 = acc[tm][tn][2], v3 = acc[tm][tn][3];
            size_t o0 = (size_t)i0 * LDQ + j0;
            size_t o1 = o0 + (size_t)8 * LDQ;
            __nv_bfloat16 h; float r0, r1, r2, r3;
            split1(v0, h, r0); split1(v1, h, r1); split1(v2, h, r2); split1(v3, h, r3);
            *(uint32_t*)(QH + o0) = pack_bf2(v0, v1);
            *(uint32_t*)(QH + o1) = pack_bf2(v2, v3);
            *(uint32_t*)(QL + o0) = pack_bf2(r0, r1);
            *(uint32_t*)(QL + o1) = pack_bf2(r2, r3);
        }
    }
}

// ============================================================
// Per-head NT GEMM K=64 (128x128, 2 CTAs/SM)
// ============================================================
template <int MODE>
__global__ void __launch_bounds__(256, 2) head_mma(
    const __nv_bfloat16* __restrict__ QH, const __nv_bfloat16* __restrict__ QL,
    int aoff, int boff,
    __nv_bfloat16* __restrict__ CH, __nv_bfloat16* __restrict__ CL,
    float* __restrict__ CF)
{
    const int h  = blockIdx.z;
    const int bi = blockIdx.y, bj = blockIdx.x;
    if (MODE != 2 && bj > bi) return;
    if (MODE == 2 && bj < bi) return;

    extern __shared__ char sm[];
    const uint32_t smb = smem_u32(sm);
    const int t = threadIdx.x;
    const int wid = t >> 5, lane = t & 31;
    const int m0 = (wid & 1) * 64;
    const int n0 = (wid >> 1) * 32;

    const int grp  = t >> 6;
    const int gg   = t & 63;
    const int col  = gg & 3;
    const int row0 = gg >> 2;
    const __nv_bfloat16* base;
    if (grp == 0)      base = QH + (size_t)(bi * 128) * LDQ + aoff + h * DH;
    else if (grp == 1) base = QL + (size_t)(bi * 128) * LDQ + aoff + h * DH;
    else if (grp == 2) base = QH + (size_t)(bj * 128) * LDQ + boff + h * DH;
    else               base = QL + (size_t)(bj * 128) * LDQ + boff + h * DH;
    const __nv_bfloat16* gsrc = base + (size_t)row0 * LDQ + col * 8;
    const uint32_t sdst = smb + grp * TILEB + row0 * PADB + col * 16;

    ISSUE_128(0, gsrc, LDQ, sdst);
    ISSUE_128(1, gsrc, LDQ, sdst);

    float acc[4][4][4] = {};
    const int lrow = lane & 15;
    const uint32_t lkoff = (uint32_t)((lane >> 4) * 16);

    CP_WAIT1();
    __syncthreads();
    {
        const uint32_t bse = smb;
        mma_chunk_128(bse, bse + TILEB, bse + 2 * TILEB, bse + 3 * TILEB,
                      m0, n0, lrow, lkoff, acc);
    }
    CP_WAIT0();
    __syncthreads();
    {
        const uint32_t bse = smb + BUFB;
        mma_chunk_128(bse, bse + TILEB, bse + 2 * TILEB, bse + 3 * TILEB,
                      m0, n0, lrow, lkoff, acc);
    }

    const size_t hb = (size_t)h * NS * NS;
    const int g  = lane >> 2;
    const int tg = lane & 3;
#pragma unroll
    for (int tm = 0; tm < 4; tm++) {
#pragma unroll
        for (int tn = 0; tn < 4; tn++) {
            const int i0 = bi * 128 + m0 + tm * 16 + g;
            const int j0 = bj * 128 + n0 + tn * 8 + tg * 2;
            float v[4];
            v[0] = acc[tm][tn][0] * SCALE; v[1] = acc[tm][tn][1] * SCALE;
            v[2] = acc[tm][tn][2] * SCALE; v[3] = acc[tm][tn][3] * SCALE;
            const int ii[4] = {i0, i0, i0 + 8, i0 + 8};
            const int jj[4] = {j0, j0 + 1, j0, j0 + 1};
#pragma unroll
            for (int q = 0; q < 4; q++) {
                if (MODE == 1) v[q] = (jj[q] <= ii[q]) ? v[q] : 0.0f;
                if (MODE == 2) v[q] = (jj[q] >  ii[q]) ? fast_sigmoid(v[q]) : 0.0f;
            }
            size_t o0 = hb + (size_t)i0 * NS + j0;
            size_t o1 = o0 + (size_t)8 * NS;
            if (MODE == 3) {
                *(float2*)(CF + o0) = make_float2(v[0], v[1]);
                *(float2*)(CF + o1) = make_float2(v[2], v[3]);
            } else {
                __nv_bfloat16 hh; float r[4];
                split1(v[0], hh, r[0]); split1(v[1], hh, r[1]);
                split1(v[2], hh, r[2]); split1(v[3], hh, r[3]);
                *(uint32_t*)(CH + o0) = pack_bf2(v[0], v[1]);
                *(uint32_t*)(CH + o1) = pack_bf2(v[2], v[3]);
                *(uint32_t*)(CL + o0) = pack_bf2(r[0], r[1]);
                *(uint32_t*)(CL + o1) = pack_bf2(r[2], r[3]);
            }
        }
    }
}

// ============================================================
// Su (128x128, 2 CTAs/SM), fused SC -= silu(Su).
// Super-block CTA remap for L2 operand reuse.
// ============================================================
__global__ void __launch_bounds__(256, 2) su_fuse_mma(
    const __nv_bfloat16* __restrict__ T1H, const __nv_bfloat16* __restrict__ T1L,
    const __nv_bfloat16* __restrict__ LKH, const __nv_bfloat16* __restrict__ LKL,
    float* __restrict__ SC)
{
    const int h = blockIdx.z;
    const int tlin = blockIdx.y * 16 + blockIdx.x;
    const int sup = tlin >> 4, inr = tlin & 15;
    const int bi = ((sup >> 2) << 2) | (inr >> 2);
    const int bk = ((sup & 3) << 2) | (inr & 3);
    if (bk > bi) return;

    extern __shared__ char sm[];
    const uint32_t smb = smem_u32(sm);
    const int t = threadIdx.x;
    const int wid = t >> 5, lane = t & 31;
    const int m0 = (wid & 1) * 64;
    const int n0 = (wid >> 1) * 32;

    const size_t hb = (size_t)h * NS * NS;
    const __nv_bfloat16* srcs[4] = {
        T1H + hb + (size_t)(bi * 128) * NS,
        T1L + hb + (size_t)(bi * 128) * NS,
        LKH + hb + (size_t)(bk * 128) * NS,
        LKL + hb + (size_t)(bk * 128) * NS
    };

    const int grp  = t >> 6;
    const int gg   = t & 63;
    const int col  = gg & 3;
    const int row0 = gg >> 2;
    const __nv_bfloat16* gsrc = srcs[grp] + (size_t)row0 * NS + (size_t)bk * 128 + col * 8;
    const uint32_t sdst = smb + grp * TILEB + row0 * PADB + col * 16;

    const int nCh = 4 * (bi - bk + 1);
    ISSUE_128(0, gsrc, NS, sdst);

    float acc[4][4][4] = {};
    const int lrow = lane & 15;
    const uint32_t lkoff = (uint32_t)((lane >> 4) * 16);

    for (int c = 0; c < nCh; c++) {
        CP_WAIT0();
        __syncthreads();
        if (c + 1 < nCh) ISSUE_128(c + 1, gsrc, NS, sdst);
        const uint32_t bse = smb + (c & 1) * BUFB;
        mma_chunk_128(bse, bse + TILEB, bse + 2 * TILEB, bse + 3 * TILEB,
                      m0, n0, lrow, lkoff, acc);
    }

    const int g  = lane >> 2;
    const int tg = lane & 3;
#pragma unroll
    for (int tm = 0; tm < 4; tm++) {
#pragma unroll
        for (int tn = 0; tn < 4; tn++) {
            const int i0 = bi * 128 + m0 + tm * 16 + g;
            const int j0 = bk * 128 + n0 + tn * 8 + tg * 2;
            float* p0 = SC + hb + (size_t)i0 * NS + j0;
            float* p1 = p0 + (size_t)8 * NS;
            float2 c0 = *(float2*)p0;
            float2 c1 = *(float2*)p1;
            c0.x -= fast_silu(acc[tm][tn][0]);
            c0.y -= fast_silu(acc[tm][tn][1]);
            c1.x -= fast_silu(acc[tm][tn][2]);
            c1.y -= fast_silu(acc[tm][tn][3]);
            *(float2*)p0 = c0;
            *(float2*)p1 = c1;
        }
    }
}

// ============================================================
// Row softmax -> split bf16 attn (fixed-trip loops: ev[] in regs)
// ============================================================
__global__ void row_softmax_bf(const float* __restrict__ SC,
                               __nv_bfloat16* __restrict__ AH,
                               __nv_bfloat16* __restrict__ AL) {
    const int h = blockIdx.y, i = blockIdx.x;
    const float* row = SC + (size_t)h * NS * NS + (size_t)i * NS;
    __nv_bfloat16* rh = AH + (size_t)h * NS * NS + (size_t)i * NS;
    __nv_bfloat16* rl = AL + (size_t)h * NS * NS + (size_t)i * NS;
    const int t = threadIdx.x;
    const int len = i + 1;

    __shared__ float red[256];

    float lmax = -1e30f;
#pragma unroll
    for (int q = 0; q < 8; q++) {
        int j = t + q * 256;
        if (j < len) lmax = fmaxf(lmax, row[j]);
    }
    red[t] = lmax; __syncthreads();
    for (int s = 128; s > 0; s >>= 1) { if (t < s) red[t] = fmaxf(red[t], red[t + s]); __syncthreads(); }
    const float bmax = red[0];
    __syncthreads();

    float ev[8];
    float lsum = 0.0f;
#pragma unroll
    for (int q = 0; q < 8; q++) {
        int j = t + q * 256;
        float e = 0.0f;
        if (j < len) e = __expf(row[j] - bmax);
        ev[q] = e;
        lsum += e;
    }
    red[t] = lsum; __syncthreads();
    for (int s = 128; s > 0; s >>= 1) { if (t < s) red[t] += red[t + s]; __syncthreads(); }
    const float inv = __fdividef(1.0f, red[0]);

#pragma unroll
    for (int q = 0; q < 8; q++) {
        int j = t + q * 256;
        if (j < len) {
            float p = ev[q] * inv;
            __nv_bfloat16 hh; float r;
            split1(p, hh, r);
            rh[j] = hh;
            rl[j] = __float2bfloat16_rn(r);
        }
    }
    const int padEnd = ((i >> 7) + 1) << 7;
    const __nv_bfloat16 z = __float2bfloat16_rn(0.0f);
    for (int j = len + t; j < padEnd; j += 256) { rh[j] = z; rl[j] = z; }
}

// ============================================================
// AV: ctx = attn @ vc. 128x64 tiles, 2-stage, 3 CTAs/SM.
// ============================================================
__global__ void __launch_bounds__(256, 3) av_mma(
    const __nv_bfloat16* __restrict__ ATH, const __nv_bfloat16* __restrict__ ATL,
    const __nv_bfloat16* __restrict__ VTH, const __nv_bfloat16* __restrict__ VTL,
    __nv_bfloat16* __restrict__ CTH, __nv_bfloat16* __restrict__ CTL)
{
    const int h = blockIdx.y, bi = blockIdx.x;
    extern __shared__ char sm[];
    const uint32_t smb = smem_u32(sm);
    const int t = threadIdx.x;
    const int wid = t >> 5, lane = t & 31;
    const int m0 = (wid & 3) * 32;
    const int n0 = (wid >> 2) * 32;

    const size_t hb = (size_t)h * NS * NS;
    const __nv_bfloat16* gAh = ATH + hb + (size_t)(bi * 128) * NS;
    const __nv_bfloat16* gAl = ATL + hb + (size_t)(bi * 128) * NS;
    const __nv_bfloat16* gBh = VTH + (size_t)(h * DH) * NS;
    const __nv_bfloat16* gBl = VTL + (size_t)(h * DH) * NS;

    const int arow = t >> 1;
    const int ac0  = (t & 1) * 2;
    const int brow = t >> 2;
    const int bc0  = t & 3;

#define AV_ISSUE(c)                                                             \
    do {                                                                        \
        const size_t j0 = (size_t)(c) * 32;                                     \
        const uint32_t bb = smb + ((c) & 1) * AV_STAGE;                         \
        const __nv_bfloat16* pah = gAh + (size_t)arow * NS + j0 + ac0 * 8;      \
        const __nv_bfloat16* pal = gAl + (size_t)arow * NS + j0 + ac0 * 8;      \
        const uint32_t sA = bb + arow * PADB + ac0 * 16;                        \
        CPASYNC16(sA,                        pah);                              \
        CPASYNC16(sA + 16,                   pah + 8);                          \
        CPASYNC16(sA + 128 * PADB,           pal);                              \
        CPASYNC16(sA + 128 * PADB + 16,      pal + 8);                          \
        const __nv_bfloat16* pbh = gBh + (size_t)brow * NS + j0 + bc0 * 8;      \
        const __nv_bfloat16* pbl = gBl + (size_t)brow * NS + j0 + bc0 * 8;      \
        const uint32_t sB = bb + 256 * PADB + brow * PADB + bc0 * 16;           \
        CPASYNC16(sB,             pbh);                                         \
        CPASYNC16(sB + 64 * PADB, pbl);                                         \
        CP_COMMIT();                                                            \
    } while (0)

    const int nCh = 4 * (bi + 1);
    AV_ISSUE(0);

    float acc[2][4][4] = {};
    const int lrow = lane & 15;
    const uint32_t lkoff = (uint32_t)((lane >> 4) * 16);

    for (int c = 0; c < nCh; c++) {
        CP_WAIT0();
        __syncthreads();
        if (c + 1 < nCh) AV_ISSUE(c + 1);

        const uint32_t bse = smb + (c & 1) * AV_STAGE;
        mma_chunk_64(bse, bse + 128 * PADB, bse + 256 * PADB, bse + 320 * PADB,
                     m0, n0, lrow, lkoff, acc);
    }

    const int g  = lane >> 2;
    const int tg = lane & 3;
#pragma unroll
    for (int tm = 0; tm < 2; tm++) {
#pragma unroll
        for (int tn = 0; tn < 4; tn++) {
            const int i0 = bi * 128 + m0 + tm * 16 + g;
            const int d0 = n0 + tn * 8 + tg * 2;
            size_t o0 = (size_t)i0 * DIMM + h * DH + d0;
            size_t o1 = o0 + (size_t)8 * DIMM;
            float v0 = acc[tm][tn][0], v1 = acc[tm][tn][1];
            float v2 = acc[tm][tn][2], v3 = acc[tm][tn][3];
            __nv_bfloat16 hh; float r0, r1, r2, r3;
            split1(v0, hh, r0); split1(v1, hh, r1); split1(v2, hh, r2); split1(v3, hh, r3);
            *(uint32_t*)(CTH + o0) = pack_bf2(v0, v1);
            *(uint32_t*)(CTH + o1) = pack_bf2(v2, v3);
            *(uint32_t*)(CTL + o0) = pack_bf2(r0, r1);
            *(uint32_t*)(CTL + o1) = pack_bf2(r2, r3);
        }
    }
}

// ============================================================
// out = ctx @ Wout. 128x64 tiles, 2-stage, 3 CTAs/SM.
// ============================================================
__global__ void __launch_bounds__(256, 3) out_mma(
    const __nv_bfloat16* __restrict__ AH0, const __nv_bfloat16* __restrict__ AL0,
    const __nv_bfloat16* __restrict__ BH0, const __nv_bfloat16* __restrict__ BL0,
    float* __restrict__ C)
{
    const int bm = blockIdx.y, bn = blockIdx.x;
    extern __shared__ char sm[];
    const uint32_t smb = smem_u32(sm);
    const int t = threadIdx.x;
    const int wid = t >> 5, lane = t & 31;
    const int m0 = (wid & 3) * 32;
    const int n0 = (wid >> 2) * 32;

    const __nv_bfloat16* gAh = AH0 + (size_t)(bm * 128) * DIMM;
    const __nv_bfloat16* gAl = AL0 + (size_t)(bm * 128) * DIMM;
    const __nv_bfloat16* gBh = BH0 + (size_t)(bn * 64) * DIMM;
    const __nv_bfloat16* gBl = BL0 + (size_t)(bn * 64) * DIMM;

    const int arow = t >> 1;
    const int ac0  = (t & 1) * 2;
    const int brow = t >> 2;
    const int bc0  = t & 3;

#define OUT_ISSUE(c)                                                            \
    do {                                                                        \
        const size_t j0 = (size_t)(c) * 32;                                     \
        const uint32_t bb = smb + ((c) & 1) * AV_STAGE;                         \
        const __nv_bfloat16* pah = gAh + (size_t)arow * DIMM + j0 + ac0 * 8;    \
        const __nv_bfloat16* pal = gAl + (size_t)arow * DIMM + j0 + ac0 * 8;    \
        const uint32_t sA = bb + arow * PADB + ac0 * 16;                        \
        CPASYNC16(sA,                        pah);                              \
        CPASYNC16(sA + 16,                   pah + 8);                          \
        CPASYNC16(sA + 128 * PADB,           pal);                              \
        CPASYNC16(sA + 128 * PADB + 16,      pal + 8);                          \
        const __nv_bfloat16* pbh = gBh + (size_t)brow * DIMM + j0 + bc0 * 8;    \
        const __nv_bfloat16* pbl = gBl + (size_t)brow * DIMM + j0 + bc0 * 8;    \
        const uint32_t sB = bb + 256 * PADB + brow * PADB + bc0 * 16;           \
        CPASYNC16(sB,             pbh);                                         \
        CPASYNC16(sB + 64 * PADB, pbl);                                         \
        CP_COMMIT();                                                            \
    } while (0)

    OUT_ISSUE(0);

    float acc[2][4][4] = {};
    const int lrow = lane & 15;
    const uint32_t lkoff = (uint32_t)((lane >> 4) * 16);

    for (int c = 0; c < 32; c++) {
        CP_WAIT0();
        __syncthreads();
        if (c + 1 < 32) OUT_ISSUE(c + 1);

        const uint32_t bse = smb + (c & 1) * AV_STAGE;
        mma_chunk_64(bse, bse + 128 * PADB, bse + 256 * PADB, bse + 320 * PADB,
                     m0, n0, lrow, lkoff, acc);
    }

    const int g  = lane >> 2;
    const int tg = lane & 3;
#pragma unroll
    for (int tm = 0; tm < 2; tm++) {
#pragma unroll
        for (int tn = 0; tn < 4; tn++) {
            const int i0 = bm * 128 + m0 + tm * 16 + g;
            const int j0 = bn * 64 + n0 + tn * 8 + tg * 2;
            size_t o0 = (size_t)i0 * DIMM + j0;
            size_t o1 = o0 + (size_t)8 * DIMM;
            *(float2*)(C + o0) = make_float2(acc[tm][tn][0], acc[tm][tn][1]);
            *(float2*)(C + o1) = make_float2(acc[tm][tn][2], acc[tm][tn][3]);
        }
    }
}

// ============================================================
extern "C" void kernel_launch(void* const* d_in, const int* in_sizes, int n_in,
                              void* d_out, int out_size) {
    const float* x    = (const float*)d_in[0];
    const float* Wqkv = (const float*)d_in[1];
    const float* Wout = (const float*)d_in[2];
    float* out = (float*)d_out;

    float *sc;
    __nv_bfloat16 *qh, *ql, *xh, *xl, *wqh, *wql, *t1h, *t1l, *lkh, *lkl;
    __nv_bfloat16 *vth, *vtl, *cth, *ctl, *woh, *wol;
    cudaGetSymbolAddress((void**)&qh,  g_qh);
    cudaGetSymbolAddress((void**)&ql,  g_ql);
    cudaGetSymbolAddress((void**)&xh,  g_xh);
    cudaGetSymbolAddress((void**)&xl,  g_xl);
    cudaGetSymbolAddress((void**)&wqh, g_wqh);
    cudaGetSymbolAddress((void**)&wql, g_wql);
    cudaGetSymbolAddress((void**)&t1h, g_t1h);
    cudaGetSymbolAddress((void**)&t1l, g_t1l);
    cudaGetSymbolAddress((void**)&lkh, g_lkh);
    cudaGetSymbolAddress((void**)&lkl, g_lkl);
    cudaGetSymbolAddress((void**)&sc,  g_sc);
    cudaGetSymbolAddress((void**)&vth, g_vth);
    cudaGetSymbolAddress((void**)&vtl, g_vtl);
    cudaGetSymbolAddress((void**)&cth, g_cth);
    cudaGetSymbolAddress((void**)&ctl, g_ctl);
    cudaGetSymbolAddress((void**)&woh, g_woh);
    cudaGetSymbolAddress((void**)&wol, g_wol);

    cudaFuncSetAttribute(qkv_mma,     cudaFuncAttributeMaxDynamicSharedMemorySize, QK_SMEM);
    cudaFuncSetAttribute(su_fuse_mma, cudaFuncAttributeMaxDynamicSharedMemorySize, DBUF_SMEM);
    cudaFuncSetAttribute(out_mma,     cudaFuncAttributeMaxDynamicSharedMemorySize, AV_SMEM2);
    cudaFuncSetAttribute(av_mma,      cudaFuncAttributeMaxDynamicSharedMemorySize, AV_SMEM2);
    cudaFuncSetAttribute(head_mma<1>, cudaFuncAttributeMaxDynamicSharedMemorySize, DBUF_SMEM);
    cudaFuncSetAttribute(head_mma<2>, cudaFuncAttributeMaxDynamicSharedMemorySize, DBUF_SMEM);
    cudaFuncSetAttribute(head_mma<3>, cudaFuncAttributeMaxDynamicSharedMemorySize, DBUF_SMEM);

    // One-time stream/event creation (first call is the uncaptured
    // correctness run; subsequent captured calls reuse them).
    static cudaStream_t s2 = nullptr;
    static cudaEvent_t ev0 = nullptr, evQ = nullptr, ev2 = nullptr;
    if (s2 == nullptr) {
        cudaStreamCreateWithFlags(&s2, cudaStreamNonBlocking);
        cudaEventCreateWithFlags(&ev0, cudaEventDisableTiming);
        cudaEventCreateWithFlags(&evQ, cudaEventDisableTiming);
        cudaEventCreateWithFlags(&ev2, cudaEventDisableTiming);
    }

    const dim3 thr(256);

    // ---- fork: s2 joins capture via ev0 ----
    cudaEventRecord(ev0, 0);
    cudaStreamWaitEvent(s2, ev0, 0);

    // s2: Wout transpose-split (independent until out_mma)
    conv_split_T<<<dim3(DIMM / 32, DIMM / 32), dim3(32, 8), 0, s2>>>(Wout, woh, wol, DIMM, DIMM);

    // default: input splits + qkv
    conv_split  <<<(NS * DIMM + 255) / 256, thr>>>(x, xh, xl, NS * DIMM);
    conv_split_T<<<dim3(LDQ / 32, DIMM / 32), dim3(32, 8)>>>(Wqkv, wqh, wql, DIMM, LDQ);
    qkv_mma<<<dim3(LDQ / 128, NS / 64), thr, QK_SMEM>>>(xh, xl, wqh, wql, qh, ql);
    cudaEventRecord(evQ, 0);

    // s2 branch (after qkv): vc^T split + lookahead head
    cudaStreamWaitEvent(s2, evQ, 0);
    conv_vT<<<dim3(NS / 32, DH / 32, NH), dim3(32, 8), 0, s2>>>(qh, ql, vth, vtl);
    {
        const dim3 gHead(NS / 128, NS / 128, NH);
        head_mma<2><<<gHead, thr, DBUF_SMEM, s2>>>(qh, ql, 0 * 1024, 1 * 1024, lkh, lkl, nullptr);
    }
    cudaEventRecord(ev2, s2);

    // default branch: term1 + Sc heads (overlap with s2 branch)
    const dim3 gHead(NS / 128, NS / 128, NH);
    head_mma<1><<<gHead, thr, DBUF_SMEM>>>(qh, ql, 3 * 1024, 2 * 1024, t1h, t1l, nullptr);
    head_mma<3><<<gHead, thr, DBUF_SMEM>>>(qh, ql, 3 * 1024, 4 * 1024, nullptr, nullptr, sc);

    // ---- join: default waits for s2 branch before su ----
    cudaStreamWaitEvent(0, ev2, 0);

    // 3) Su (super-block scheduled), fused scores = Sc - silu(Su)
    su_fuse_mma<<<gHead, thr, DBUF_SMEM>>>(t1h, t1l, lkh, lkl, sc);

    // 4) softmax -> attn split bf16 (reuses t1h/t1l)
    row_softmax_bf<<<dim3(NS, NH), thr>>>(sc, t1h, t1l);

    // 5) ctx = attn @ vc
    av_mma<<<dim3(NS / 128, NH), thr, AV_SMEM2>>>(t1h, t1l, vth, vtl, cth, ctl);

    // 6) out = ctx @ W_out
    out_mma<<<dim3(DIMM / 64, NS / 128), thr, AV_SMEM2>>>(cth, ctl, woh, wol, out);
}